// round 13
// baseline (speedup 1.0000x reference)
#include <cuda_runtime.h>
#include <cuda_bf16.h>
#include <math.h>
#include <stdint.h>

// Problem constants
#define Bq    2
#define Nq    8192
#define Kn    16
#define CINc  128
#define CRc   128
#define Dd    256
#define COUTc 256
#define EPSc  1e-5f
#define NEGc  0.2f
#define LOG2E 1.44269504088896f

#define NPTS  (Bq * Nq)        // 16384 points
#define PPB   8                // points per block (attn kernel)
#define NBLK  (NPTS / PPB)     // 2048 blocks
#define NTHRA 64               // attn: 2 warps; warp w owns points 4w..4w+3
#define NTHRG 128              // gemm threads

// Output layout (float32, concatenated)
#define OFF_XYZ   0
#define SZ_XYZ    (Bq * Nq * 3)
#define OFF_OUT   (OFF_XYZ + SZ_XYZ)
#define SZ_OUT    (Bq * Nq * COUTc)
#define OFF_ORF   (OFF_OUT + SZ_OUT)
#define SZ_ORF    (Bq * Nq * Kn * 10)
#define OFF_IDX   (OFF_ORF + SZ_ORF)
#define SZ_IDX    (Bq * Nq * Kn)

// ---- attn kernel shared layout (32-bit words) ----
// PS_FB=132 (pad 4 words): conflict-free ldmatrix. Do not reduce.
#define PS_FB    132
#define SMA_FEAT 0
#define SMA_RELW (SMA_FEAT + 128 * PS_FB)   // 16896
#define SMA_RELB (SMA_RELW + 10 * CRc)      // 18176
#define SMA_IDX  (SMA_RELB + CRc)           // 18304
#define SMA_TOT  (SMA_IDX + 128)            // 18432 words
#define SMA_BYTES (SMA_TOT * 4)             // 73728 B -> 3 blocks/SM

// ---- gemm kernel (r9-proven version) ----
#define GM_TILE  32            // points per gemm block
#define PS_A     388           // As row stride (floats)
#define GSM_BYTES (GM_TILE * PS_A * 4)   // 49664 B -> 4 blocks/SM

// Device globals (no allocation allowed)
__device__ float d_relWf[10 * CRc];
__device__ float d_relB[CRc];
__device__ float d_biasC[COUTc];
// attn_W * log2(e) in bf16 m16n8k16 B-fragment layout:
// e = ((nch*16 + s)*4 + j2)*32 + lane ; uint4 = {b0(j),b1(j),b0(j+1),b1(j+1)}
__device__ uint4 d_attnFrag[4 * 16 * 4 * 32];        // 128 KB
// [outWf ; scWf] (BN-folded) in tf32 m16n8k8 B-fragment layout
__device__ uint4 d_wFrag[48 * 16 * 32];              // 384 KB
// pooled scratch [NPTS][256]
__device__ float d_pooled[(size_t)NPTS * Dd];        // 16.8 MB

__device__ __forceinline__ uint32_t to_tf32(float x) {
    uint32_t r;
    asm("cvt.rna.tf32.f32 %0, %1;" : "=r"(r) : "f"(x));
    return r;
}
__device__ __forceinline__ float to_tf32f(float x) {
    return __uint_as_float(to_tf32(x));
}
__device__ __forceinline__ uint32_t pack_bf2(float lo, float hi) {
    __nv_bfloat162 h = __floats2bfloat162_rn(lo, hi);
    return *reinterpret_cast<uint32_t*>(&h);
}
__device__ __forceinline__ void ldmatrix_x4(uint32_t* d, uint32_t addr) {
    asm volatile("ldmatrix.sync.aligned.m8n8.x4.shared.b16 {%0,%1,%2,%3}, [%4];"
                 : "=r"(d[0]), "=r"(d[1]), "=r"(d[2]), "=r"(d[3]) : "r"(addr));
}
__device__ __forceinline__ uint32_t smem_u32(const void* p) {
    return (uint32_t)__cvta_generic_to_shared(p);
}
__device__ __forceinline__ float2 bf2f(uint32_t u) {
    return __bfloat1622float2(*reinterpret_cast<__nv_bfloat162*>(&u));
}

#define MMA_BF16(acc, A, b0, b1) \
    asm volatile( \
        "mma.sync.aligned.m16n8k16.row.col.f32.bf16.bf16.f32 " \
        "{%0,%1,%2,%3}, {%4,%5,%6,%7}, {%8,%9}, {%0,%1,%2,%3};" \
        : "+f"((acc)[0]), "+f"((acc)[1]), "+f"((acc)[2]), "+f"((acc)[3]) \
        : "r"((A)[0]), "r"((A)[1]), "r"((A)[2]), "r"((A)[3]), "r"(b0), "r"(b1))

// folded weight for the combined [outW;scW] GEMM
__device__ __forceinline__ float wc_fold(int k, int n,
    const float* out_W, const float* out_g, const float* out_v,
    const float* sc_W,  const float* sc_g,  const float* sc_v)
{
    if (k < Dd)  return out_W[k * COUTc + n] * out_g[n] * rsqrtf(out_v[n] + EPSc);
    return sc_W[(k - Dd) * COUTc + n] * sc_g[n] * rsqrtf(sc_v[n] + EPSc);
}

// ---------------------------------------------------------------------------
// Setup: fold BN, build fragment tables.
// ---------------------------------------------------------------------------
__global__ void fuse_kernel(
    const float* __restrict__ rel_W, const float* __restrict__ rel_b,
    const float* __restrict__ rel_g, const float* __restrict__ rel_be,
    const float* __restrict__ rel_m, const float* __restrict__ rel_v,
    const float* __restrict__ out_W, const float* __restrict__ out_b,
    const float* __restrict__ out_g, const float* __restrict__ out_be,
    const float* __restrict__ out_m, const float* __restrict__ out_v,
    const float* __restrict__ sc_W,  const float* __restrict__ sc_b,
    const float* __restrict__ sc_g,  const float* __restrict__ sc_be,
    const float* __restrict__ sc_m,  const float* __restrict__ sc_v,
    const float* __restrict__ attn_W)
{
    int t0 = blockIdx.x * blockDim.x + threadIdx.x;
    int stride = gridDim.x * blockDim.x;

    for (int i = t0; i < 10 * CRc; i += stride) {
        int c = i & (CRc - 1);
        d_relWf[i] = rel_W[i] * rel_g[c] * rsqrtf(rel_v[c] + EPSc);
    }
    for (int i = t0; i < CRc; i += stride) {
        float A = rel_g[i] * rsqrtf(rel_v[i] + EPSc);
        d_relB[i] = (rel_b[i] - rel_m[i]) * A + rel_be[i];
    }
    for (int i = t0; i < COUTc; i += stride) {
        float Ao = out_g[i] * rsqrtf(out_v[i] + EPSc);
        float As = sc_g[i] * rsqrtf(sc_v[i] + EPSc);
        d_biasC[i] = (out_b[i] - out_m[i]) * Ao + out_be[i]
                   + (sc_b[i] - sc_m[i]) * As + sc_be[i];
    }

    // attn bf16 fragment table, pre-scaled by log2(e)
    for (int e = t0; e < 4 * 16 * 4 * 32; e += stride) {
        int lane = e & 31, j2 = (e >> 5) & 3, s = (e >> 7) & 15, nch = e >> 11;
        int g = lane >> 2, tt = lane & 3, k0 = s * 16;
        int n0 = nch * 64 + (2 * j2) * 8 + g;
        int n1 = n0 + 8;
        uint4 v;
        v.x = pack_bf2(LOG2E * attn_W[(k0 + 2*tt)     * Dd + n0],
                       LOG2E * attn_W[(k0 + 2*tt + 1) * Dd + n0]);
        v.y = pack_bf2(LOG2E * attn_W[(k0 + 2*tt + 8) * Dd + n0],
                       LOG2E * attn_W[(k0 + 2*tt + 9) * Dd + n0]);
        v.z = pack_bf2(LOG2E * attn_W[(k0 + 2*tt)     * Dd + n1],
                       LOG2E * attn_W[(k0 + 2*tt + 1) * Dd + n1]);
        v.w = pack_bf2(LOG2E * attn_W[(k0 + 2*tt + 8) * Dd + n1],
                       LOG2E * attn_W[(k0 + 2*tt + 9) * Dd + n1]);
        d_attnFrag[e] = v;
    }

    // combined [outW;scW] tf32 fragment table
    for (int e = t0; e < 48 * 16 * 32; e += stride) {
        int lane = e & 31, j2 = (e >> 5) & 15, s = e >> 9;
        int g = lane >> 2, tt = lane & 3, k0 = s * 8;
        int n0 = (2 * j2) * 8 + g;
        int n1 = n0 + 8;
        uint4 v;
        v.x = to_tf32(wc_fold(k0 + tt,     n0, out_W, out_g, out_v, sc_W, sc_g, sc_v));
        v.y = to_tf32(wc_fold(k0 + tt + 4, n0, out_W, out_g, out_v, sc_W, sc_g, sc_v));
        v.z = to_tf32(wc_fold(k0 + tt,     n1, out_W, out_g, out_v, sc_W, sc_g, sc_v));
        v.w = to_tf32(wc_fold(k0 + tt + 4, n1, out_W, out_g, out_v, sc_W, sc_g, sc_v));
        d_wFrag[e] = v;
    }
}

// ---------------------------------------------------------------------------
// Passthrough copies
// ---------------------------------------------------------------------------
__global__ void copy_kernel(const float* __restrict__ xyz,
                            const float* __restrict__ orf,
                            const int*   __restrict__ nidx,
                            float* __restrict__ out)
{
    int t0 = blockIdx.x * blockDim.x + threadIdx.x;
    int stride = gridDim.x * blockDim.x;
    const float4* xs = (const float4*)xyz;
    float4* xd = (float4*)(out + OFF_XYZ);
    for (int i = t0; i < SZ_XYZ / 4; i += stride) xd[i] = xs[i];
    const float4* os = (const float4*)orf;
    float4* od = (float4*)(out + OFF_ORF);
    for (int i = t0; i < SZ_ORF / 4; i += stride) od[i] = os[i];
    float* id = out + OFF_IDX;
    for (int i = t0; i < SZ_IDX; i += stride) id[i] = (float)nidx[i];
}

// ---------------------------------------------------------------------------
// Attention kernel: 8 points/block, 64 threads (2 warps); warp w owns
// points 4w..4w+3. Each B fragment load feeds 16 MMAs (4 A-tiles x 2 j).
// B traffic per point is half of the 2-pt/warp design.
// ---------------------------------------------------------------------------
__global__ __launch_bounds__(NTHRA, 3)
void lfa_attn_kernel(const float* __restrict__ feature,
                     const float* __restrict__ orf,
                     const int*   __restrict__ nidx)
{
    extern __shared__ uint32_t smem[];
    uint32_t* feat_b = smem + SMA_FEAT;           // [128][PS_FB] bf16x2
    float* relW_s = (float*)(smem + SMA_RELW);    // [10][128]
    float* relB_s = (float*)(smem + SMA_RELB);    // [128]
    int*   idx_s  = (int*)(smem + SMA_IDX);       // [128]

    const int tid = threadIdx.x;
    const int p0  = blockIdx.x * PPB;
    const int b   = p0 >> 13;

    // ---- Stage rel weights + neighbor indices ----
    idx_s[tid] = nidx[p0 * Kn + tid];
    idx_s[tid + 64] = nidx[p0 * Kn + tid + 64];
    for (int i = tid; i < 10 * CRc; i += NTHRA) relW_s[i] = d_relWf[i];
    relB_s[tid] = d_relB[tid];
    relB_s[tid + 64] = d_relB[tid + 64];
    __syncthreads();

    // ---- Gather neighbor features -> bf16 pairs (128 rows x 128 cols) ----
    const float* fbase = feature + (size_t)b * Nq * CINc;
    for (int i = tid; i < 128 * 32; i += NTHRA) {
        int r = i >> 5, c4 = i & 31;
        float4 v = *((const float4*)(fbase + (size_t)idx_s[r] * CINc) + c4);
        uint2 pk;
        pk.x = pack_bf2(v.x, v.y);
        pk.y = pack_bf2(v.z, v.w);
        *(uint2*)&feat_b[r * PS_FB + c4 * 2] = pk;
    }

    // ---- rel MLP: two rows per thread, orf in registers ----
    #pragma unroll
    for (int rr = 0; rr < 2; rr++) {
        const int r = tid + rr * 64;
        float o[10];
        const float* orow = orf + (size_t)p0 * 160 + r * 10;
        #pragma unroll
        for (int d = 0; d < 10; d++) o[d] = orow[d];
        uint32_t* frow = &feat_b[r * PS_FB + 64];
        #pragma unroll 4
        for (int c2 = 0; c2 < 64; c2++) {
            float a0 = relB_s[2 * c2], a1 = relB_s[2 * c2 + 1];
            #pragma unroll
            for (int d = 0; d < 10; d++) {
                float2 wv = *(const float2*)&relW_s[d * CRc + 2 * c2];
                a0 += o[d] * wv.x;
                a1 += o[d] * wv.y;
            }
            a0 = (a0 >= 0.f) ? a0 : NEGc * a0;
            a1 = (a1 >= 0.f) ? a1 : NEGc * a1;
            frow[c2] = pack_bf2(a0, a1);
        }
    }
    __syncthreads();

    const int w    = tid >> 5;          // warp 0..1, owns points 4w..4w+3
    const int lane = tid & 31;
    const int g    = lane >> 2;
    const int t    = lane & 3;

    // ldmatrix per-lane row addresses for 4 points
    const int row16 = (lane & 7) | (((lane >> 3) & 1) << 3);
    const int khalf = lane >> 4;
    const uint32_t fb_base = smem_u32(feat_b);
    uint32_t abase[4];
    int prow0[4];
    float* poolrow[4];
    #pragma unroll
    for (int pi = 0; pi < 4; pi++) {
        const int pl = 4 * w + pi;     // local point
        abase[pi] = fb_base + ((pl * 16 + row16) * PS_FB + khalf * 4) * 4;
        prow0[pi] = (pl * 16 + g) * PS_FB;
        poolrow[pi] = d_pooled + (size_t)(p0 + pl) * Dd;
    }

    #pragma unroll 1
    for (int nch = 0; nch < 4; nch++) {
        float acc[4][8][4];
        #pragma unroll
        for (int pi = 0; pi < 4; pi++)
            #pragma unroll
            for (int j = 0; j < 8; j++)
                #pragma unroll
                for (int q = 0; q < 4; q++) acc[pi][j][q] = 0.f;

        const uint4* bfrag = d_attnFrag + (size_t)(nch * 16) * 128 + lane;

        #pragma unroll 4
        for (int s = 0; s < 16; s++) {
            uint32_t A[4][4];
            #pragma unroll
            for (int pi = 0; pi < 4; pi++)
                ldmatrix_x4(A[pi], abase[pi] + s * 32);
            const uint4* bs = bfrag + s * 128;
            #pragma unroll
            for (int j2 = 0; j2 < 4; j2++) {
                uint4 bv = bs[j2 * 32];
                #pragma unroll
                for (int pi = 0; pi < 4; pi++) {
                    MMA_BF16(acc[pi][2*j2],     A[pi], bv.x, bv.y);
                    MMA_BF16(acc[pi][2*j2 + 1], A[pi], bv.z, bv.w);
                }
            }
        }

        // ---- Epilogue: softmax over k + pooling (f from smem) ----
        #pragma unroll
        for (int pi = 0; pi < 4; pi++) {
            const int pr0 = prow0[pi];
            const int pr8 = pr0 + 8 * PS_FB;
            float* prow = poolrow[pi];
            #pragma unroll
            for (int j = 0; j < 8; j++) {
                float e0 = exp2f(acc[pi][j][0]);   // logits pre-scaled by log2(e)
                float e1 = exp2f(acc[pi][j][1]);
                float e2 = exp2f(acc[pi][j][2]);
                float e3 = exp2f(acc[pi][j][3]);

                uint32_t u01 = feat_b[pr0 + nch * 32 + j * 4 + t];
                uint32_t u23 = feat_b[pr8 + nch * 32 + j * 4 + t];
                float2 f01 = bf2f(u01);
                float2 f23 = bf2f(u23);

                float s0  = e0 + e2;
                float s1  = e1 + e3;
                float pp0 = e0 * f01.x + e2 * f23.x;
                float pp1 = e1 * f01.y + e3 * f23.y;

                #pragma unroll
                for (int d = 4; d <= 16; d <<= 1) {
                    s0  += __shfl_xor_sync(0xffffffffu, s0, d);
                    s1  += __shfl_xor_sync(0xffffffffu, s1, d);
                    pp0 += __shfl_xor_sync(0xffffffffu, pp0, d);
                    pp1 += __shfl_xor_sync(0xffffffffu, pp1, d);
                }

                if (g == 0) {
                    const int C = nch * 64 + j * 8 + 2 * t;
                    *(float2*)&prow[C] =
                        make_float2(__fdividef(pp0, s0), __fdividef(pp1, s1));
                }
            }
        }
    }
}

// ---------------------------------------------------------------------------
// Final GEMM (r9-proven): out = leaky([pooled | feature] @ [outWf;scWf] + bias)
// 128 threads, 4 warps (warp = cs); each warp 2 m16 row-tiles. PS_A row layout.
// ---------------------------------------------------------------------------
__global__ __launch_bounds__(NTHRG, 4)
void lfa_gemm_kernel(const float* __restrict__ feature,
                     float*       __restrict__ out_feat)
{
    extern __shared__ float As[];      // [32][PS_A]

    const int tid = threadIdx.x;
    const int m0b = blockIdx.x * GM_TILE;

    for (int i = tid; i < GM_TILE * 96; i += NTHRG) {
        int row = i / 96, q = i % 96;
        int m = m0b + row;
        float4 v;
        if (q < 64) v = *((const float4*)(d_pooled + (size_t)m * Dd) + q);
        else        v = *((const float4*)(feature + (size_t)m * CINc) + (q - 64));
        v.x = to_tf32f(v.x); v.y = to_tf32f(v.y);
        v.z = to_tf32f(v.z); v.w = to_tf32f(v.w);
        *(float4*)&As[row * PS_A + q * 4] = v;
    }
    __syncthreads();

    const int cs   = tid >> 5;
    const int lane = tid & 31;
    const int g    = lane >> 2;
    const int t    = lane & 3;
    const int arow0 = g * PS_A;
    const int arow8 = arow0 + 8 * PS_A;
    const int brow0 = (16 + g) * PS_A;
    const int brow8 = brow0 + 8 * PS_A;

    float acc0[8][4], acc1[8][4];
    #pragma unroll
    for (int j = 0; j < 8; j++)
        #pragma unroll
        for (int q = 0; q < 4; q++) { acc0[j][q] = 0.f; acc1[j][q] = 0.f; }

    const uint4* bfrag = d_wFrag + (size_t)(cs * 4) * 32 + lane;

    #pragma unroll 6
    for (int s = 0; s < 48; s++) {
        const int k0 = s * 8;
        uint32_t a0 = __float_as_uint(As[arow0 + k0 + t]);
        uint32_t a1 = __float_as_uint(As[arow8 + k0 + t]);
        uint32_t a2 = __float_as_uint(As[arow0 + k0 + t + 4]);
        uint32_t a3 = __float_as_uint(As[arow8 + k0 + t + 4]);
        uint32_t b0 = __float_as_uint(As[brow0 + k0 + t]);
        uint32_t b1 = __float_as_uint(As[brow8 + k0 + t]);
        uint32_t b2 = __float_as_uint(As[brow0 + k0 + t + 4]);
        uint32_t b3 = __float_as_uint(As[brow8 + k0 + t + 4]);
        const uint4* bs = bfrag + (size_t)s * 16 * 32;
        #pragma unroll
        for (int j2 = 0; j2 < 4; j2++) {
            uint4 bv = bs[j2 * 32];
            asm volatile(
                "mma.sync.aligned.m16n8k8.row.col.f32.tf32.tf32.f32 "
                "{%0,%1,%2,%3}, {%4,%5,%6,%7}, {%8,%9}, {%0,%1,%2,%3};"
                : "+f"(acc0[2*j2][0]), "+f"(acc0[2*j2][1]),
                  "+f"(acc0[2*j2][2]), "+f"(acc0[2*j2][3])
                : "r"(a0), "r"(a1), "r"(a2), "r"(a3), "r"(bv.x), "r"(bv.y));
            asm volatile(
                "mma.sync.aligned.m16n8k8.row.col.f32.tf32.tf32.f32 "
                "{%0,%1,%2,%3}, {%4,%5,%6,%7}, {%8,%9}, {%0,%1,%2,%3};"
                : "+f"(acc0[2*j2+1][0]), "+f"(acc0[2*j2+1][1]),
                  "+f"(acc0[2*j2+1][2]), "+f"(acc0[2*j2+1][3])
                : "r"(a0), "r"(a1), "r"(a2), "r"(a3), "r"(bv.z), "r"(bv.w));
            asm volatile(
                "mma.sync.aligned.m16n8k8.row.col.f32.tf32.tf32.f32 "
                "{%0,%1,%2,%3}, {%4,%5,%6,%7}, {%8,%9}, {%0,%1,%2,%3};"
                : "+f"(acc1[2*j2][0]), "+f"(acc1[2*j2][1]),
                  "+f"(acc1[2*j2][2]), "+f"(acc1[2*j2][3])
                : "r"(b0), "r"(b1), "r"(b2), "r"(b3), "r"(bv.x), "r"(bv.y));
            asm volatile(
                "mma.sync.aligned.m16n8k8.row.col.f32.tf32.tf32.f32 "
                "{%0,%1,%2,%3}, {%4,%5,%6,%7}, {%8,%9}, {%0,%1,%2,%3};"
                : "+f"(acc1[2*j2+1][0]), "+f"(acc1[2*j2+1][1]),
                  "+f"(acc1[2*j2+1][2]), "+f"(acc1[2*j2+1][3])
                : "r"(b0), "r"(b1), "r"(b2), "r"(b3), "r"(bv.z), "r"(bv.w));
        }
    }

    #pragma unroll
    for (int rt = 0; rt < 2; rt++) {
        float (*acc)[4] = rt ? acc1 : acc0;
        const int mrow0 = m0b + rt * 16 + g;
        #pragma unroll
        for (int j = 0; j < 8; j++) {
            const int n0 = cs * 64 + j * 8 + 2 * t;
            float2 bias = *(const float2*)&d_biasC[n0];
            float o0 = acc[j][0] + bias.x;
            float o1 = acc[j][1] + bias.y;
            float o2 = acc[j][2] + bias.x;
            float o3 = acc[j][3] + bias.y;
            o0 = (o0 >= 0.f) ? o0 : NEGc * o0;
            o1 = (o1 >= 0.f) ? o1 : NEGc * o1;
            o2 = (o2 >= 0.f) ? o2 : NEGc * o2;
            o3 = (o3 >= 0.f) ? o3 : NEGc * o3;
            *(float2*)&out_feat[(size_t)mrow0 * COUTc + n0]       = make_float2(o0, o1);
            *(float2*)&out_feat[(size_t)(mrow0 + 8) * COUTc + n0] = make_float2(o2, o3);
        }
    }
}

// ---------------------------------------------------------------------------
extern "C" void kernel_launch(void* const* d_in, const int* in_sizes, int n_in,
                              void* d_out, int out_size)
{
    const float* xyz     = (const float*)d_in[0];
    const float* feature = (const float*)d_in[1];
    const float* orf     = (const float*)d_in[2];
    const int*   nidx    = (const int*)  d_in[3];
    const float* rel_W   = (const float*)d_in[4];
    const float* rel_b   = (const float*)d_in[5];
    const float* rel_g   = (const float*)d_in[6];
    const float* rel_be  = (const float*)d_in[7];
    const float* rel_m   = (const float*)d_in[8];
    const float* rel_v   = (const float*)d_in[9];
    const float* attn_W  = (const float*)d_in[10];
    const float* out_W   = (const float*)d_in[11];
    const float* out_b   = (const float*)d_in[12];
    const float* out_g   = (const float*)d_in[13];
    const float* out_be  = (const float*)d_in[14];
    const float* out_m   = (const float*)d_in[15];
    const float* out_v   = (const float*)d_in[16];
    const float* sc_W    = (const float*)d_in[17];
    const float* sc_b    = (const float*)d_in[18];
    const float* sc_g    = (const float*)d_in[19];
    const float* sc_be   = (const float*)d_in[20];
    const float* sc_m    = (const float*)d_in[21];
    const float* sc_v    = (const float*)d_in[22];

    float* out = (float*)d_out;

    cudaFuncSetAttribute(lfa_attn_kernel,
                         cudaFuncAttributeMaxDynamicSharedMemorySize, SMA_BYTES);
    cudaFuncSetAttribute(lfa_gemm_kernel,
                         cudaFuncAttributeMaxDynamicSharedMemorySize, GSM_BYTES);

    fuse_kernel<<<512, 256>>>(rel_W, rel_b, rel_g, rel_be, rel_m, rel_v,
                              out_W, out_b, out_g, out_be, out_m, out_v,
                              sc_W,  sc_b,  sc_g,  sc_be,  sc_m,  sc_v,
                              attn_W);

    lfa_attn_kernel<<<NBLK, NTHRA, SMA_BYTES>>>(feature, orf, nidx);

    lfa_gemm_kernel<<<NPTS / GM_TILE, NTHRG, GSM_BYTES>>>(feature, out + OFF_OUT);

    copy_kernel<<<512, 256>>>(xyz, orf, nidx, out);
}

// round 14
// speedup vs baseline: 1.4506x; 1.4506x over previous
#include <cuda_runtime.h>
#include <cuda_bf16.h>
#include <math.h>
#include <stdint.h>

// Problem constants
#define Bq    2
#define Nq    8192
#define Kn    16
#define CINc  128
#define CRc   128
#define Dd    256
#define COUTc 256
#define EPSc  1e-5f
#define NEGc  0.2f
#define LOG2E 1.44269504088896f

#define NPTS  (Bq * Nq)        // 16384 points
#define PPB   8                // points per block (attn kernel)
#define NBLK  (NPTS / PPB)     // 2048 blocks
#define NTHR  128              // 4 warps; warp w owns points 2w, 2w+1

// Output layout (float32, concatenated)
#define OFF_XYZ   0
#define SZ_XYZ    (Bq * Nq * 3)
#define OFF_OUT   (OFF_XYZ + SZ_XYZ)
#define SZ_OUT    (Bq * Nq * COUTc)
#define OFF_ORF   (OFF_OUT + SZ_OUT)
#define SZ_ORF    (Bq * Nq * Kn * 10)
#define OFF_IDX   (OFF_ORF + SZ_ORF)
#define SZ_IDX    (Bq * Nq * Kn)

// ---- attn kernel shared layout (32-bit words) ----
// PS_FB=132 (pad 4 words): conflict-free ldmatrix. Do not reduce.
#define PS_FB    132
#define SMA_FEAT 0
#define SMA_RELW (SMA_FEAT + 128 * PS_FB)   // 16896
#define SMA_RELB (SMA_RELW + 10 * CRc)      // 18176
#define SMA_IDX  (SMA_RELB + CRc)           // 18304
#define SMA_TOT  (SMA_IDX + 128)            // 18432 words
#define SMA_BYTES (SMA_TOT * 4)             // 73728 B -> 3 blocks/SM

// ---- gemm kernel (r9-proven version) ----
#define GM_TILE  32            // points per gemm block
#define PS_A     388           // As row stride (floats)
#define GSM_BYTES (GM_TILE * PS_A * 4)   // 49664 B -> 4 blocks/SM

// Device globals (no allocation allowed)
__device__ float d_relWf[10 * CRc];
__device__ float d_relB[CRc];
__device__ float d_biasC[COUTc];
// attn_W * log2(e) in bf16 m16n8k16 B-fragment layout:
// e = ((nch*16 + s)*4 + j2)*32 + lane ; uint4 = {b0(j),b1(j),b0(j+1),b1(j+1)}
__device__ uint4 d_attnFrag[4 * 16 * 4 * 32];        // 128 KB
// [outWf ; scWf] (BN-folded) in tf32 m16n8k8 B-fragment layout
__device__ uint4 d_wFrag[48 * 16 * 32];              // 384 KB
// pooled scratch [NPTS][256]
__device__ float d_pooled[(size_t)NPTS * Dd];        // 16.8 MB

__device__ __forceinline__ uint32_t to_tf32(float x) {
    uint32_t r;
    asm("cvt.rna.tf32.f32 %0, %1;" : "=r"(r) : "f"(x));
    return r;
}
__device__ __forceinline__ float to_tf32f(float x) {
    return __uint_as_float(to_tf32(x));
}
__device__ __forceinline__ uint32_t pack_bf2(float lo, float hi) {
    __nv_bfloat162 h = __floats2bfloat162_rn(lo, hi);
    return *reinterpret_cast<uint32_t*>(&h);
}
__device__ __forceinline__ void ldmatrix_x4(uint32_t* d, uint32_t addr) {
    asm volatile("ldmatrix.sync.aligned.m8n8.x4.shared.b16 {%0,%1,%2,%3}, [%4];"
                 : "=r"(d[0]), "=r"(d[1]), "=r"(d[2]), "=r"(d[3]) : "r"(addr));
}
__device__ __forceinline__ uint32_t smem_u32(const void* p) {
    return (uint32_t)__cvta_generic_to_shared(p);
}
__device__ __forceinline__ float2 bf2f(uint32_t u) {
    return __bfloat1622float2(*reinterpret_cast<__nv_bfloat162*>(&u));
}

// folded weight for the combined [outW;scW] GEMM
__device__ __forceinline__ float wc_fold(int k, int n,
    const float* out_W, const float* out_g, const float* out_v,
    const float* sc_W,  const float* sc_g,  const float* sc_v)
{
    if (k < Dd)  return out_W[k * COUTc + n] * out_g[n] * rsqrtf(out_v[n] + EPSc);
    return sc_W[(k - Dd) * COUTc + n] * sc_g[n] * rsqrtf(sc_v[n] + EPSc);
}

// ---------------------------------------------------------------------------
// Setup: fold BN, build fragment tables, passthrough copies (merged: r9 style)
// ---------------------------------------------------------------------------
__global__ void fuse_and_copy_kernel(
    const float* __restrict__ rel_W, const float* __restrict__ rel_b,
    const float* __restrict__ rel_g, const float* __restrict__ rel_be,
    const float* __restrict__ rel_m, const float* __restrict__ rel_v,
    const float* __restrict__ out_W, const float* __restrict__ out_b,
    const float* __restrict__ out_g, const float* __restrict__ out_be,
    const float* __restrict__ out_m, const float* __restrict__ out_v,
    const float* __restrict__ sc_W,  const float* __restrict__ sc_b,
    const float* __restrict__ sc_g,  const float* __restrict__ sc_be,
    const float* __restrict__ sc_m,  const float* __restrict__ sc_v,
    const float* __restrict__ attn_W,
    const float* __restrict__ xyz,   const float* __restrict__ orf,
    const int*   __restrict__ nidx,  float* __restrict__ out)
{
    int t0 = blockIdx.x * blockDim.x + threadIdx.x;
    int stride = gridDim.x * blockDim.x;

    for (int i = t0; i < 10 * CRc; i += stride) {
        int c = i & (CRc - 1);
        d_relWf[i] = rel_W[i] * rel_g[c] * rsqrtf(rel_v[c] + EPSc);
    }
    for (int i = t0; i < CRc; i += stride) {
        float A = rel_g[i] * rsqrtf(rel_v[i] + EPSc);
        d_relB[i] = (rel_b[i] - rel_m[i]) * A + rel_be[i];
    }
    for (int i = t0; i < COUTc; i += stride) {
        float Ao = out_g[i] * rsqrtf(out_v[i] + EPSc);
        float As = sc_g[i] * rsqrtf(sc_v[i] + EPSc);
        d_biasC[i] = (out_b[i] - out_m[i]) * Ao + out_be[i]
                   + (sc_b[i] - sc_m[i]) * As + sc_be[i];
    }

    // attn bf16 fragment table, pre-scaled by log2(e) (softmax exp -> exp2)
    for (int e = t0; e < 4 * 16 * 4 * 32; e += stride) {
        int lane = e & 31, j2 = (e >> 5) & 3, s = (e >> 7) & 15, nch = e >> 11;
        int g = lane >> 2, tt = lane & 3, k0 = s * 16;
        int n0 = nch * 64 + (2 * j2) * 8 + g;
        int n1 = n0 + 8;
        uint4 v;
        v.x = pack_bf2(LOG2E * attn_W[(k0 + 2*tt)     * Dd + n0],
                       LOG2E * attn_W[(k0 + 2*tt + 1) * Dd + n0]);
        v.y = pack_bf2(LOG2E * attn_W[(k0 + 2*tt + 8) * Dd + n0],
                       LOG2E * attn_W[(k0 + 2*tt + 9) * Dd + n0]);
        v.z = pack_bf2(LOG2E * attn_W[(k0 + 2*tt)     * Dd + n1],
                       LOG2E * attn_W[(k0 + 2*tt + 1) * Dd + n1]);
        v.w = pack_bf2(LOG2E * attn_W[(k0 + 2*tt + 8) * Dd + n1],
                       LOG2E * attn_W[(k0 + 2*tt + 9) * Dd + n1]);
        d_attnFrag[e] = v;
    }

    // combined [outW;scW] tf32 fragment table
    for (int e = t0; e < 48 * 16 * 32; e += stride) {
        int lane = e & 31, j2 = (e >> 5) & 15, s = e >> 9;
        int g = lane >> 2, tt = lane & 3, k0 = s * 8;
        int n0 = (2 * j2) * 8 + g;
        int n1 = n0 + 8;
        uint4 v;
        v.x = to_tf32(wc_fold(k0 + tt,     n0, out_W, out_g, out_v, sc_W, sc_g, sc_v));
        v.y = to_tf32(wc_fold(k0 + tt + 4, n0, out_W, out_g, out_v, sc_W, sc_g, sc_v));
        v.z = to_tf32(wc_fold(k0 + tt,     n1, out_W, out_g, out_v, sc_W, sc_g, sc_v));
        v.w = to_tf32(wc_fold(k0 + tt + 4, n1, out_W, out_g, out_v, sc_W, sc_g, sc_v));
        d_wFrag[e] = v;
    }

    // Passthrough copies
    const float4* xs = (const float4*)xyz;
    float4* xd = (float4*)(out + OFF_XYZ);
    for (int i = t0; i < SZ_XYZ / 4; i += stride) xd[i] = xs[i];
    const float4* os = (const float4*)orf;
    float4* od = (float4*)(out + OFF_ORF);
    for (int i = t0; i < SZ_ORF / 4; i += stride) od[i] = os[i];
    float* id = out + OFF_IDX;
    for (int i = t0; i < SZ_IDX; i += stride) id[i] = (float)nidx[i];
}

// ---------------------------------------------------------------------------
// Attention kernel: 8 points/block, 128 threads; warp w owns points 2w, 2w+1.
// 3 blocks/SM; B frags via __ldg from global (barrier-free); A via ldmatrix;
// s-loop fully unrolled for maximum LDG front-batching (MLP).
// ---------------------------------------------------------------------------
__global__ __launch_bounds__(NTHR, 3)
void lfa_attn_kernel(const float* __restrict__ feature,
                     const float* __restrict__ orf,
                     const int*   __restrict__ nidx)
{
    extern __shared__ uint32_t smem[];
    uint32_t* feat_b = smem + SMA_FEAT;           // [128][PS_FB] bf16x2
    float* relW_s = (float*)(smem + SMA_RELW);    // [10][128]
    float* relB_s = (float*)(smem + SMA_RELB);    // [128]
    int*   idx_s  = (int*)(smem + SMA_IDX);       // [128]

    const int tid = threadIdx.x;
    const int p0  = blockIdx.x * PPB;
    const int b   = p0 >> 13;

    // ---- Stage rel weights + neighbor indices ----
    idx_s[tid] = nidx[p0 * Kn + tid];
    for (int i = tid; i < 10 * CRc; i += NTHR) relW_s[i] = d_relWf[i];
    if (tid < CRc) relB_s[tid] = d_relB[tid];
    __syncthreads();

    // ---- Gather neighbor features -> bf16 pairs (128 rows x 128 cols) ----
    const float* fbase = feature + (size_t)b * Nq * CINc;
    for (int i = tid; i < 128 * 32; i += NTHR) {
        int r = i >> 5, c4 = i & 31;
        float4 v = *((const float4*)(fbase + (size_t)idx_s[r] * CINc) + c4);
        uint2 pk;
        pk.x = pack_bf2(v.x, v.y);
        pk.y = pack_bf2(v.z, v.w);
        *(uint2*)&feat_b[r * PS_FB + c4 * 2] = pk;
    }

    // ---- rel MLP: one row per thread, orf in registers ----
    {
        const int r = tid;
        float o[10];
        const float* orow = orf + (size_t)p0 * 160 + r * 10;
        #pragma unroll
        for (int d = 0; d < 10; d++) o[d] = orow[d];
        uint32_t* frow = &feat_b[r * PS_FB + 64];
        #pragma unroll 4
        for (int c2 = 0; c2 < 64; c2++) {
            float a0 = relB_s[2 * c2], a1 = relB_s[2 * c2 + 1];
            #pragma unroll
            for (int d = 0; d < 10; d++) {
                float2 wv = *(const float2*)&relW_s[d * CRc + 2 * c2];
                a0 += o[d] * wv.x;
                a1 += o[d] * wv.y;
            }
            a0 = (a0 >= 0.f) ? a0 : NEGc * a0;
            a1 = (a1 >= 0.f) ? a1 : NEGc * a1;
            frow[c2] = pack_bf2(a0, a1);
        }
    }
    __syncthreads();

    const int w    = tid >> 5;
    const int lane = tid & 31;
    const int g    = lane >> 2;
    const int t    = lane & 3;

    // ldmatrix per-lane row addresses for points 2w, 2w+1
    const int row16 = (lane & 7) | (((lane >> 3) & 1) << 3);   // 0..15
    const int khalf = lane >> 4;                                // 0..1
    const uint32_t fb_base = smem_u32(feat_b);
    const uint32_t abase0 = fb_base + (((2*w)   * 16 + row16) * PS_FB + khalf * 4) * 4;
    const uint32_t abase1 = fb_base + (((2*w+1) * 16 + row16) * PS_FB + khalf * 4) * 4;

    // feat epilogue rows for both points
    const int prow0_0 = ((2*w)   * 16 + g) * PS_FB, prow8_0 = prow0_0 + 8 * PS_FB;
    const int prow0_1 = ((2*w+1) * 16 + g) * PS_FB, prow8_1 = prow0_1 + 8 * PS_FB;
    float* poolrow0 = d_pooled + (size_t)(p0 + 2*w)     * Dd;
    float* poolrow1 = d_pooled + (size_t)(p0 + 2*w + 1) * Dd;

    #pragma unroll 1
    for (int nch = 0; nch < 4; nch++) {
        float acc0[8][4], acc1[8][4];
        #pragma unroll
        for (int j = 0; j < 8; j++)
            #pragma unroll
            for (int q = 0; q < 4; q++) { acc0[j][q] = 0.f; acc1[j][q] = 0.f; }

        const uint4* bfrag = d_attnFrag + (size_t)(nch * 16) * 128 + lane;

        #pragma unroll
        for (int s = 0; s < 16; s++) {
            uint32_t A0[4], A1[4];
            ldmatrix_x4(A0, abase0 + s * 32);
            ldmatrix_x4(A1, abase1 + s * 32);
            const uint4* bs = bfrag + s * 128;
            #pragma unroll
            for (int j2 = 0; j2 < 4; j2++) {
                uint4 bv = __ldg(bs + j2 * 32);
                asm volatile(
                    "mma.sync.aligned.m16n8k16.row.col.f32.bf16.bf16.f32 "
                    "{%0,%1,%2,%3}, {%4,%5,%6,%7}, {%8,%9}, {%0,%1,%2,%3};"
                    : "+f"(acc0[2*j2][0]), "+f"(acc0[2*j2][1]),
                      "+f"(acc0[2*j2][2]), "+f"(acc0[2*j2][3])
                    : "r"(A0[0]), "r"(A0[1]), "r"(A0[2]), "r"(A0[3]), "r"(bv.x), "r"(bv.y));
                asm volatile(
                    "mma.sync.aligned.m16n8k16.row.col.f32.bf16.bf16.f32 "
                    "{%0,%1,%2,%3}, {%4,%5,%6,%7}, {%8,%9}, {%0,%1,%2,%3};"
                    : "+f"(acc1[2*j2][0]), "+f"(acc1[2*j2][1]),
                      "+f"(acc1[2*j2][2]), "+f"(acc1[2*j2][3])
                    : "r"(A1[0]), "r"(A1[1]), "r"(A1[2]), "r"(A1[3]), "r"(bv.x), "r"(bv.y));
                asm volatile(
                    "mma.sync.aligned.m16n8k16.row.col.f32.bf16.bf16.f32 "
                    "{%0,%1,%2,%3}, {%4,%5,%6,%7}, {%8,%9}, {%0,%1,%2,%3};"
                    : "+f"(acc0[2*j2+1][0]), "+f"(acc0[2*j2+1][1]),
                      "+f"(acc0[2*j2+1][2]), "+f"(acc0[2*j2+1][3])
                    : "r"(A0[0]), "r"(A0[1]), "r"(A0[2]), "r"(A0[3]), "r"(bv.z), "r"(bv.w));
                asm volatile(
                    "mma.sync.aligned.m16n8k16.row.col.f32.bf16.bf16.f32 "
                    "{%0,%1,%2,%3}, {%4,%5,%6,%7}, {%8,%9}, {%0,%1,%2,%3};"
                    : "+f"(acc1[2*j2+1][0]), "+f"(acc1[2*j2+1][1]),
                      "+f"(acc1[2*j2+1][2]), "+f"(acc1[2*j2+1][3])
                    : "r"(A1[0]), "r"(A1[1]), "r"(A1[2]), "r"(A1[3]), "r"(bv.z), "r"(bv.w));
            }
        }

        // ---- Epilogue: softmax over k + pooling (shfl butterfly), both pts ----
        #pragma unroll
        for (int pt = 0; pt < 2; pt++) {
            float (*acc)[4] = pt ? acc1 : acc0;
            const int prow0 = pt ? prow0_1 : prow0_0;
            const int prow8 = pt ? prow8_1 : prow8_0;
            float* poolrow = pt ? poolrow1 : poolrow0;
            #pragma unroll
            for (int j = 0; j < 8; j++) {
                float e0 = exp2f(acc[j][0]);   // logits pre-scaled by log2(e)
                float e1 = exp2f(acc[j][1]);
                float e2 = exp2f(acc[j][2]);
                float e3 = exp2f(acc[j][3]);

                uint32_t u01 = feat_b[prow0 + nch * 32 + j * 4 + t];
                uint32_t u23 = feat_b[prow8 + nch * 32 + j * 4 + t];
                float2 f01 = bf2f(u01);
                float2 f23 = bf2f(u23);

                float s0  = e0 + e2;
                float s1  = e1 + e3;
                float pp0 = e0 * f01.x + e2 * f23.x;
                float pp1 = e1 * f01.y + e3 * f23.y;

                #pragma unroll
                for (int d = 4; d <= 16; d <<= 1) {
                    s0  += __shfl_xor_sync(0xffffffffu, s0, d);
                    s1  += __shfl_xor_sync(0xffffffffu, s1, d);
                    pp0 += __shfl_xor_sync(0xffffffffu, pp0, d);
                    pp1 += __shfl_xor_sync(0xffffffffu, pp1, d);
                }

                if (g == 0) {
                    const int C = nch * 64 + j * 8 + 2 * t;
                    *(float2*)&poolrow[C] =
                        make_float2(__fdividef(pp0, s0), __fdividef(pp1, s1));
                }
            }
        }
    }
}

// ---------------------------------------------------------------------------
// Final GEMM (r9-proven): out = leaky([pooled | feature] @ [outWf;scWf] + bias)
// 128 threads, 4 warps (warp = cs); each warp 2 m16 row-tiles.
// ---------------------------------------------------------------------------
__global__ __launch_bounds__(NTHR, 4)
void lfa_gemm_kernel(const float* __restrict__ feature,
                     float*       __restrict__ out_feat)
{
    extern __shared__ float As[];      // [32][PS_A]

    const int tid = threadIdx.x;
    const int m0b = blockIdx.x * GM_TILE;

    for (int i = tid; i < GM_TILE * 96; i += NTHR) {
        int row = i / 96, q = i % 96;
        int m = m0b + row;
        float4 v;
        if (q < 64) v = *((const float4*)(d_pooled + (size_t)m * Dd) + q);
        else        v = *((const float4*)(feature + (size_t)m * CINc) + (q - 64));
        v.x = to_tf32f(v.x); v.y = to_tf32f(v.y);
        v.z = to_tf32f(v.z); v.w = to_tf32f(v.w);
        *(float4*)&As[row * PS_A + q * 4] = v;
    }
    __syncthreads();

    const int cs   = tid >> 5;
    const int lane = tid & 31;
    const int g    = lane >> 2;
    const int t    = lane & 3;
    const int arow0 = g * PS_A;
    const int arow8 = arow0 + 8 * PS_A;
    const int brow0 = (16 + g) * PS_A;
    const int brow8 = brow0 + 8 * PS_A;

    float acc0[8][4], acc1[8][4];
    #pragma unroll
    for (int j = 0; j < 8; j++)
        #pragma unroll
        for (int q = 0; q < 4; q++) { acc0[j][q] = 0.f; acc1[j][q] = 0.f; }

    const uint4* bfrag = d_wFrag + (size_t)(cs * 4) * 32 + lane;

    #pragma unroll 6
    for (int s = 0; s < 48; s++) {
        const int k0 = s * 8;
        uint32_t a0 = __float_as_uint(As[arow0 + k0 + t]);
        uint32_t a1 = __float_as_uint(As[arow8 + k0 + t]);
        uint32_t a2 = __float_as_uint(As[arow0 + k0 + t + 4]);
        uint32_t a3 = __float_as_uint(As[arow8 + k0 + t + 4]);
        uint32_t b0 = __float_as_uint(As[brow0 + k0 + t]);
        uint32_t b1 = __float_as_uint(As[brow8 + k0 + t]);
        uint32_t b2 = __float_as_uint(As[brow0 + k0 + t + 4]);
        uint32_t b3 = __float_as_uint(As[brow8 + k0 + t + 4]);
        const uint4* bs = bfrag + (size_t)s * 16 * 32;
        #pragma unroll
        for (int j2 = 0; j2 < 4; j2++) {
            uint4 bv = __ldg(bs + j2 * 32);
            asm volatile(
                "mma.sync.aligned.m16n8k8.row.col.f32.tf32.tf32.f32 "
                "{%0,%1,%2,%3}, {%4,%5,%6,%7}, {%8,%9}, {%0,%1,%2,%3};"
                : "+f"(acc0[2*j2][0]), "+f"(acc0[2*j2][1]),
                  "+f"(acc0[2*j2][2]), "+f"(acc0[2*j2][3])
                : "r"(a0), "r"(a1), "r"(a2), "r"(a3), "r"(bv.x), "r"(bv.y));
            asm volatile(
                "mma.sync.aligned.m16n8k8.row.col.f32.tf32.tf32.f32 "
                "{%0,%1,%2,%3}, {%4,%5,%6,%7}, {%8,%9}, {%0,%1,%2,%3};"
                : "+f"(acc0[2*j2+1][0]), "+f"(acc0[2*j2+1][1]),
                  "+f"(acc0[2*j2+1][2]), "+f"(acc0[2*j2+1][3])
                : "r"(a0), "r"(a1), "r"(a2), "r"(a3), "r"(bv.z), "r"(bv.w));
            asm volatile(
                "mma.sync.aligned.m16n8k8.row.col.f32.tf32.tf32.f32 "
                "{%0,%1,%2,%3}, {%4,%5,%6,%7}, {%8,%9}, {%0,%1,%2,%3};"
                : "+f"(acc1[2*j2][0]), "+f"(acc1[2*j2][1]),
                  "+f"(acc1[2*j2][2]), "+f"(acc1[2*j2][3])
                : "r"(b0), "r"(b1), "r"(b2), "r"(b3), "r"(bv.x), "r"(bv.y));
            asm volatile(
                "mma.sync.aligned.m16n8k8.row.col.f32.tf32.tf32.f32 "
                "{%0,%1,%2,%3}, {%4,%5,%6,%7}, {%8,%9}, {%0,%1,%2,%3};"
                : "+f"(acc1[2*j2+1][0]), "+f"(acc1[2*j2+1][1]),
                  "+f"(acc1[2*j2+1][2]), "+f"(acc1[2*j2+1][3])
                : "r"(b0), "r"(b1), "r"(b2), "r"(b3), "r"(bv.z), "r"(bv.w));
        }
    }

    #pragma unroll
    for (int rt = 0; rt < 2; rt++) {
        float (*acc)[4] = rt ? acc1 : acc0;
        const int mrow0 = m0b + rt * 16 + g;
        #pragma unroll
        for (int j = 0; j < 8; j++) {
            const int n0 = cs * 64 + j * 8 + 2 * t;
            float2 bias = *(const float2*)&d_biasC[n0];
            float o0 = acc[j][0] + bias.x;
            float o1 = acc[j][1] + bias.y;
            float o2 = acc[j][2] + bias.x;
            float o3 = acc[j][3] + bias.y;
            o0 = (o0 >= 0.f) ? o0 : NEGc * o0;
            o1 = (o1 >= 0.f) ? o1 : NEGc * o1;
            o2 = (o2 >= 0.f) ? o2 : NEGc * o2;
            o3 = (o3 >= 0.f) ? o3 : NEGc * o3;
            *(float2*)&out_feat[(size_t)mrow0 * COUTc + n0]       = make_float2(o0, o1);
            *(float2*)&out_feat[(size_t)(mrow0 + 8) * COUTc + n0] = make_float2(o2, o3);
        }
    }
}

// ---------------------------------------------------------------------------
extern "C" void kernel_launch(void* const* d_in, const int* in_sizes, int n_in,
                              void* d_out, int out_size)
{
    const float* xyz     = (const float*)d_in[0];
    const float* feature = (const float*)d_in[1];
    const float* orf     = (const float*)d_in[2];
    const int*   nidx    = (const int*)  d_in[3];
    const float* rel_W   = (const float*)d_in[4];
    const float* rel_b   = (const float*)d_in[5];
    const float* rel_g   = (const float*)d_in[6];
    const float* rel_be  = (const float*)d_in[7];
    const float* rel_m   = (const float*)d_in[8];
    const float* rel_v   = (const float*)d_in[9];
    const float* attn_W  = (const float*)d_in[10];
    const float* out_W   = (const float*)d_in[11];
    const float* out_b   = (const float*)d_in[12];
    const float* out_g   = (const float*)d_in[13];
    const float* out_be  = (const float*)d_in[14];
    const float* out_m   = (const float*)d_in[15];
    const float* out_v   = (const float*)d_in[16];
    const float* sc_W    = (const float*)d_in[17];
    const float* sc_b    = (const float*)d_in[18];
    const float* sc_g    = (const float*)d_in[19];
    const float* sc_be   = (const float*)d_in[20];
    const float* sc_m    = (const float*)d_in[21];
    const float* sc_v    = (const float*)d_in[22];

    float* out = (float*)d_out;

    cudaFuncSetAttribute(lfa_attn_kernel,
                         cudaFuncAttributeMaxDynamicSharedMemorySize, SMA_BYTES);
    cudaFuncSetAttribute(lfa_gemm_kernel,
                         cudaFuncAttributeMaxDynamicSharedMemorySize, GSM_BYTES);

    fuse_and_copy_kernel<<<1024, 256>>>(rel_W, rel_b, rel_g, rel_be, rel_m, rel_v,
                                        out_W, out_b, out_g, out_be, out_m, out_v,
                                        sc_W,  sc_b,  sc_g,  sc_be,  sc_m,  sc_v,
                                        attn_W, xyz, orf, nidx, out);

    lfa_attn_kernel<<<NBLK, NTHR, SMA_BYTES>>>(feature, orf, nidx);

    lfa_gemm_kernel<<<NPTS / GM_TILE, NTHR, GSM_BYTES>>>(feature, out + OFF_OUT);
}

// round 15
// speedup vs baseline: 1.4515x; 1.0006x over previous
#include <cuda_runtime.h>
#include <cuda_bf16.h>
#include <math.h>
#include <stdint.h>

// Problem constants
#define Bq    2
#define Nq    8192
#define Kn    16
#define CINc  128
#define CRc   128
#define Dd    256
#define COUTc 256
#define EPSc  1e-5f
#define NEGc  0.2f
#define LOG2E 1.44269504088896f

#define NPTS  (Bq * Nq)        // 16384 points
#define PPB   8                // points per block (attn kernel)
#define NBLK  (NPTS / PPB)     // 2048 blocks
#define NTHR  128              // 4 warps; warp w owns points 2w, 2w+1

// Output layout (float32, concatenated)
#define OFF_XYZ   0
#define SZ_XYZ    (Bq * Nq * 3)
#define OFF_OUT   (OFF_XYZ + SZ_XYZ)
#define SZ_OUT    (Bq * Nq * COUTc)
#define OFF_ORF   (OFF_OUT + SZ_OUT)
#define SZ_ORF    (Bq * Nq * Kn * 10)
#define OFF_IDX   (OFF_ORF + SZ_ORF)
#define SZ_IDX    (Bq * Nq * Kn)

// ---- attn kernel shared layout (32-bit words) ----
// PS_FB=132 (pad 4 words): conflict-free ldmatrix. Do not reduce.
#define PS_FB    132
#define SMA_FEAT 0
#define SMA_RELW (SMA_FEAT + 128 * PS_FB)   // 16896
#define SMA_RELB (SMA_RELW + 10 * CRc)      // 18176
#define SMA_IDX  (SMA_RELB + CRc)           // 18304
#define SMA_TOT  (SMA_IDX + 128)            // 18432 words
#define SMA_BYTES (SMA_TOT * 4)             // 73728 B -> 3 blocks/SM

// ---- gemm kernel (r9-proven version) ----
#define GM_TILE  32            // points per gemm block
#define PS_A     388           // As row stride (floats)
#define GSM_BYTES (GM_TILE * PS_A * 4)   // 49664 B -> 4 blocks/SM

// Device globals (no allocation allowed)
__device__ float d_relWf[10 * CRc];
__device__ float d_relB[CRc];
__device__ float d_biasC[COUTc];
// attn_W * log2(e) in bf16 m16n8k16 B-fragment layout:
// e = ((nch*16 + s)*4 + j2)*32 + lane ; uint4 = {b0(j),b1(j),b0(j+1),b1(j+1)}
__device__ uint4 d_attnFrag[4 * 16 * 4 * 32];        // 128 KB
// [outWf ; scWf] (BN-folded) in tf32 m16n8k8 B-fragment layout
__device__ uint4 d_wFrag[48 * 16 * 32];              // 384 KB
// pooled scratch [NPTS][256]
__device__ float d_pooled[(size_t)NPTS * Dd];        // 16.8 MB

__device__ __forceinline__ uint32_t to_tf32(float x) {
    uint32_t r;
    asm("cvt.rna.tf32.f32 %0, %1;" : "=r"(r) : "f"(x));
    return r;
}
__device__ __forceinline__ float to_tf32f(float x) {
    return __uint_as_float(to_tf32(x));
}
__device__ __forceinline__ uint32_t pack_bf2(float lo, float hi) {
    __nv_bfloat162 h = __floats2bfloat162_rn(lo, hi);
    return *reinterpret_cast<uint32_t*>(&h);
}
__device__ __forceinline__ void ldmatrix_x4(uint32_t* d, uint32_t addr) {
    asm volatile("ldmatrix.sync.aligned.m8n8.x4.shared.b16 {%0,%1,%2,%3}, [%4];"
                 : "=r"(d[0]), "=r"(d[1]), "=r"(d[2]), "=r"(d[3]) : "r"(addr));
}
__device__ __forceinline__ uint32_t smem_u32(const void* p) {
    return (uint32_t)__cvta_generic_to_shared(p);
}
__device__ __forceinline__ float2 bf2f(uint32_t u) {
    return __bfloat1622float2(*reinterpret_cast<__nv_bfloat162*>(&u));
}

// folded weight for the combined [outW;scW] GEMM
__device__ __forceinline__ float wc_fold(int k, int n,
    const float* out_W, const float* out_g, const float* out_v,
    const float* sc_W,  const float* sc_g,  const float* sc_v)
{
    if (k < Dd)  return out_W[k * COUTc + n] * out_g[n] * rsqrtf(out_v[n] + EPSc);
    return sc_W[(k - Dd) * COUTc + n] * sc_g[n] * rsqrtf(sc_v[n] + EPSc);
}

// ---------------------------------------------------------------------------
// Setup: fold BN, build fragment tables, passthrough copies (merged)
// ---------------------------------------------------------------------------
__global__ void fuse_and_copy_kernel(
    const float* __restrict__ rel_W, const float* __restrict__ rel_b,
    const float* __restrict__ rel_g, const float* __restrict__ rel_be,
    const float* __restrict__ rel_m, const float* __restrict__ rel_v,
    const float* __restrict__ out_W, const float* __restrict__ out_b,
    const float* __restrict__ out_g, const float* __restrict__ out_be,
    const float* __restrict__ out_m, const float* __restrict__ out_v,
    const float* __restrict__ sc_W,  const float* __restrict__ sc_b,
    const float* __restrict__ sc_g,  const float* __restrict__ sc_be,
    const float* __restrict__ sc_m,  const float* __restrict__ sc_v,
    const float* __restrict__ attn_W,
    const float* __restrict__ xyz,   const float* __restrict__ orf,
    const int*   __restrict__ nidx,  float* __restrict__ out)
{
    int t0 = blockIdx.x * blockDim.x + threadIdx.x;
    int stride = gridDim.x * blockDim.x;

    for (int i = t0; i < 10 * CRc; i += stride) {
        int c = i & (CRc - 1);
        d_relWf[i] = rel_W[i] * rel_g[c] * rsqrtf(rel_v[c] + EPSc);
    }
    for (int i = t0; i < CRc; i += stride) {
        float A = rel_g[i] * rsqrtf(rel_v[i] + EPSc);
        d_relB[i] = (rel_b[i] - rel_m[i]) * A + rel_be[i];
    }
    for (int i = t0; i < COUTc; i += stride) {
        float Ao = out_g[i] * rsqrtf(out_v[i] + EPSc);
        float As = sc_g[i] * rsqrtf(sc_v[i] + EPSc);
        d_biasC[i] = (out_b[i] - out_m[i]) * Ao + out_be[i]
                   + (sc_b[i] - sc_m[i]) * As + sc_be[i];
    }

    // attn bf16 fragment table, pre-scaled by log2(e) (softmax exp -> exp2)
    for (int e = t0; e < 4 * 16 * 4 * 32; e += stride) {
        int lane = e & 31, j2 = (e >> 5) & 3, s = (e >> 7) & 15, nch = e >> 11;
        int g = lane >> 2, tt = lane & 3, k0 = s * 16;
        int n0 = nch * 64 + (2 * j2) * 8 + g;
        int n1 = n0 + 8;
        uint4 v;
        v.x = pack_bf2(LOG2E * attn_W[(k0 + 2*tt)     * Dd + n0],
                       LOG2E * attn_W[(k0 + 2*tt + 1) * Dd + n0]);
        v.y = pack_bf2(LOG2E * attn_W[(k0 + 2*tt + 8) * Dd + n0],
                       LOG2E * attn_W[(k0 + 2*tt + 9) * Dd + n0]);
        v.z = pack_bf2(LOG2E * attn_W[(k0 + 2*tt)     * Dd + n1],
                       LOG2E * attn_W[(k0 + 2*tt + 1) * Dd + n1]);
        v.w = pack_bf2(LOG2E * attn_W[(k0 + 2*tt + 8) * Dd + n1],
                       LOG2E * attn_W[(k0 + 2*tt + 9) * Dd + n1]);
        d_attnFrag[e] = v;
    }

    // combined [outW;scW] tf32 fragment table
    for (int e = t0; e < 48 * 16 * 32; e += stride) {
        int lane = e & 31, j2 = (e >> 5) & 15, s = e >> 9;
        int g = lane >> 2, tt = lane & 3, k0 = s * 8;
        int n0 = (2 * j2) * 8 + g;
        int n1 = n0 + 8;
        uint4 v;
        v.x = to_tf32(wc_fold(k0 + tt,     n0, out_W, out_g, out_v, sc_W, sc_g, sc_v));
        v.y = to_tf32(wc_fold(k0 + tt + 4, n0, out_W, out_g, out_v, sc_W, sc_g, sc_v));
        v.z = to_tf32(wc_fold(k0 + tt,     n1, out_W, out_g, out_v, sc_W, sc_g, sc_v));
        v.w = to_tf32(wc_fold(k0 + tt + 4, n1, out_W, out_g, out_v, sc_W, sc_g, sc_v));
        d_wFrag[e] = v;
    }

    // Passthrough copies
    const float4* xs = (const float4*)xyz;
    float4* xd = (float4*)(out + OFF_XYZ);
    for (int i = t0; i < SZ_XYZ / 4; i += stride) xd[i] = xs[i];
    const float4* os = (const float4*)orf;
    float4* od = (float4*)(out + OFF_ORF);
    for (int i = t0; i < SZ_ORF / 4; i += stride) od[i] = os[i];
    float* id = out + OFF_IDX;
    for (int i = t0; i < SZ_IDX; i += stride) id[i] = (float)nidx[i];
}

// ---------------------------------------------------------------------------
// Attention kernel: 8 points/block, 128 threads; warp w owns points 2w, 2w+1.
// 3 blocks/SM; B frags via __ldg, SOFTWARE-PIPELINED one s-step ahead;
// A via ldmatrix; s-loop fully unrolled.
// ---------------------------------------------------------------------------
__global__ __launch_bounds__(NTHR, 3)
void lfa_attn_kernel(const float* __restrict__ feature,
                     const float* __restrict__ orf,
                     const int*   __restrict__ nidx)
{
    extern __shared__ uint32_t smem[];
    uint32_t* feat_b = smem + SMA_FEAT;           // [128][PS_FB] bf16x2
    float* relW_s = (float*)(smem + SMA_RELW);    // [10][128]
    float* relB_s = (float*)(smem + SMA_RELB);    // [128]
    int*   idx_s  = (int*)(smem + SMA_IDX);       // [128]

    const int tid = threadIdx.x;
    const int p0  = blockIdx.x * PPB;
    const int b   = p0 >> 13;

    // ---- Stage rel weights + neighbor indices ----
    idx_s[tid] = nidx[p0 * Kn + tid];
    for (int i = tid; i < 10 * CRc; i += NTHR) relW_s[i] = d_relWf[i];
    if (tid < CRc) relB_s[tid] = d_relB[tid];
    __syncthreads();

    // ---- Gather neighbor features -> bf16 pairs (128 rows x 128 cols) ----
    const float* fbase = feature + (size_t)b * Nq * CINc;
    for (int i = tid; i < 128 * 32; i += NTHR) {
        int r = i >> 5, c4 = i & 31;
        float4 v = *((const float4*)(fbase + (size_t)idx_s[r] * CINc) + c4);
        uint2 pk;
        pk.x = pack_bf2(v.x, v.y);
        pk.y = pack_bf2(v.z, v.w);
        *(uint2*)&feat_b[r * PS_FB + c4 * 2] = pk;
    }

    // ---- rel MLP: one row per thread, orf in registers ----
    {
        const int r = tid;
        float o[10];
        const float* orow = orf + (size_t)p0 * 160 + r * 10;
        #pragma unroll
        for (int d = 0; d < 10; d++) o[d] = orow[d];
        uint32_t* frow = &feat_b[r * PS_FB + 64];
        #pragma unroll 4
        for (int c2 = 0; c2 < 64; c2++) {
            float a0 = relB_s[2 * c2], a1 = relB_s[2 * c2 + 1];
            #pragma unroll
            for (int d = 0; d < 10; d++) {
                float2 wv = *(const float2*)&relW_s[d * CRc + 2 * c2];
                a0 += o[d] * wv.x;
                a1 += o[d] * wv.y;
            }
            a0 = (a0 >= 0.f) ? a0 : NEGc * a0;
            a1 = (a1 >= 0.f) ? a1 : NEGc * a1;
            frow[c2] = pack_bf2(a0, a1);
        }
    }
    __syncthreads();

    const int w    = tid >> 5;
    const int lane = tid & 31;
    const int g    = lane >> 2;
    const int t    = lane & 3;

    // ldmatrix per-lane row addresses for points 2w, 2w+1
    const int row16 = (lane & 7) | (((lane >> 3) & 1) << 3);   // 0..15
    const int khalf = lane >> 4;                                // 0..1
    const uint32_t fb_base = smem_u32(feat_b);
    const uint32_t abase0 = fb_base + (((2*w)   * 16 + row16) * PS_FB + khalf * 4) * 4;
    const uint32_t abase1 = fb_base + (((2*w+1) * 16 + row16) * PS_FB + khalf * 4) * 4;

    // feat epilogue rows for both points
    const int prow0_0 = ((2*w)   * 16 + g) * PS_FB, prow8_0 = prow0_0 + 8 * PS_FB;
    const int prow0_1 = ((2*w+1) * 16 + g) * PS_FB, prow8_1 = prow0_1 + 8 * PS_FB;
    float* poolrow0 = d_pooled + (size_t)(p0 + 2*w)     * Dd;
    float* poolrow1 = d_pooled + (size_t)(p0 + 2*w + 1) * Dd;

    #pragma unroll 1
    for (int nch = 0; nch < 4; nch++) {
        float acc0[8][4], acc1[8][4];
        #pragma unroll
        for (int j = 0; j < 8; j++)
            #pragma unroll
            for (int q = 0; q < 4; q++) { acc0[j][q] = 0.f; acc1[j][q] = 0.f; }

        const uint4* bfrag = d_attnFrag + (size_t)(nch * 16) * 128 + lane;

        // Software pipeline: prefetch B for step s+1 before issuing step s MMAs.
        uint4 bcur[4], bnxt[4];
        #pragma unroll
        for (int j2 = 0; j2 < 4; j2++) bcur[j2] = __ldg(bfrag + j2 * 32);

        #pragma unroll
        for (int s = 0; s < 16; s++) {
            // Prefetch next step's B fragments (full iteration of distance)
            if (s < 15) {
                const uint4* bs = bfrag + (s + 1) * 128;
                #pragma unroll
                for (int j2 = 0; j2 < 4; j2++) bnxt[j2] = __ldg(bs + j2 * 32);
            }

            uint32_t A0[4], A1[4];
            ldmatrix_x4(A0, abase0 + s * 32);
            ldmatrix_x4(A1, abase1 + s * 32);

            #pragma unroll
            for (int j2 = 0; j2 < 4; j2++) {
                uint4 bv = bcur[j2];
                asm volatile(
                    "mma.sync.aligned.m16n8k16.row.col.f32.bf16.bf16.f32 "
                    "{%0,%1,%2,%3}, {%4,%5,%6,%7}, {%8,%9}, {%0,%1,%2,%3};"
                    : "+f"(acc0[2*j2][0]), "+f"(acc0[2*j2][1]),
                      "+f"(acc0[2*j2][2]), "+f"(acc0[2*j2][3])
                    : "r"(A0[0]), "r"(A0[1]), "r"(A0[2]), "r"(A0[3]), "r"(bv.x), "r"(bv.y));
                asm volatile(
                    "mma.sync.aligned.m16n8k16.row.col.f32.bf16.bf16.f32 "
                    "{%0,%1,%2,%3}, {%4,%5,%6,%7}, {%8,%9}, {%0,%1,%2,%3};"
                    : "+f"(acc1[2*j2][0]), "+f"(acc1[2*j2][1]),
                      "+f"(acc1[2*j2][2]), "+f"(acc1[2*j2][3])
                    : "r"(A1[0]), "r"(A1[1]), "r"(A1[2]), "r"(A1[3]), "r"(bv.x), "r"(bv.y));
                asm volatile(
                    "mma.sync.aligned.m16n8k16.row.col.f32.bf16.bf16.f32 "
                    "{%0,%1,%2,%3}, {%4,%5,%6,%7}, {%8,%9}, {%0,%1,%2,%3};"
                    : "+f"(acc0[2*j2+1][0]), "+f"(acc0[2*j2+1][1]),
                      "+f"(acc0[2*j2+1][2]), "+f"(acc0[2*j2+1][3])
                    : "r"(A0[0]), "r"(A0[1]), "r"(A0[2]), "r"(A0[3]), "r"(bv.z), "r"(bv.w));
                asm volatile(
                    "mma.sync.aligned.m16n8k16.row.col.f32.bf16.bf16.f32 "
                    "{%0,%1,%2,%3}, {%4,%5,%6,%7}, {%8,%9}, {%0,%1,%2,%3};"
                    : "+f"(acc1[2*j2+1][0]), "+f"(acc1[2*j2+1][1]),
                      "+f"(acc1[2*j2+1][2]), "+f"(acc1[2*j2+1][3])
                    : "r"(A1[0]), "r"(A1[1]), "r"(A1[2]), "r"(A1[3]), "r"(bv.z), "r"(bv.w));
            }

            #pragma unroll
            for (int j2 = 0; j2 < 4; j2++) bcur[j2] = bnxt[j2];
        }

        // ---- Epilogue: softmax over k + pooling (shfl butterfly), both pts ----
        #pragma unroll
        for (int pt = 0; pt < 2; pt++) {
            float (*acc)[4] = pt ? acc1 : acc0;
            const int prow0 = pt ? prow0_1 : prow0_0;
            const int prow8 = pt ? prow8_1 : prow8_0;
            float* poolrow = pt ? poolrow1 : poolrow0;
            #pragma unroll
            for (int j = 0; j < 8; j++) {
                float e0 = exp2f(acc[j][0]);   // logits pre-scaled by log2(e)
                float e1 = exp2f(acc[j][1]);
                float e2 = exp2f(acc[j][2]);
                float e3 = exp2f(acc[j][3]);

                uint32_t u01 = feat_b[prow0 + nch * 32 + j * 4 + t];
                uint32_t u23 = feat_b[prow8 + nch * 32 + j * 4 + t];
                float2 f01 = bf2f(u01);
                float2 f23 = bf2f(u23);

                float s0  = e0 + e2;
                float s1  = e1 + e3;
                float pp0 = e0 * f01.x + e2 * f23.x;
                float pp1 = e1 * f01.y + e3 * f23.y;

                #pragma unroll
                for (int d = 4; d <= 16; d <<= 1) {
                    s0  += __shfl_xor_sync(0xffffffffu, s0, d);
                    s1  += __shfl_xor_sync(0xffffffffu, s1, d);
                    pp0 += __shfl_xor_sync(0xffffffffu, pp0, d);
                    pp1 += __shfl_xor_sync(0xffffffffu, pp1, d);
                }

                if (g == 0) {
                    const int C = nch * 64 + j * 8 + 2 * t;
                    *(float2*)&poolrow[C] =
                        make_float2(__fdividef(pp0, s0), __fdividef(pp1, s1));
                }
            }
        }
    }
}

// ---------------------------------------------------------------------------
// Final GEMM (r9-proven): out = leaky([pooled | feature] @ [outWf;scWf] + bias)
// 128 threads, 4 warps (warp = cs); each warp 2 m16 row-tiles.
// ---------------------------------------------------------------------------
__global__ __launch_bounds__(NTHR, 4)
void lfa_gemm_kernel(const float* __restrict__ feature,
                     float*       __restrict__ out_feat)
{
    extern __shared__ float As[];      // [32][PS_A]

    const int tid = threadIdx.x;
    const int m0b = blockIdx.x * GM_TILE;

    for (int i = tid; i < GM_TILE * 96; i += NTHR) {
        int row = i / 96, q = i % 96;
        int m = m0b + row;
        float4 v;
        if (q < 64) v = *((const float4*)(d_pooled + (size_t)m * Dd) + q);
        else        v = *((const float4*)(feature + (size_t)m * CINc) + (q - 64));
        v.x = to_tf32f(v.x); v.y = to_tf32f(v.y);
        v.z = to_tf32f(v.z); v.w = to_tf32f(v.w);
        *(float4*)&As[row * PS_A + q * 4] = v;
    }
    __syncthreads();

    const int cs   = tid >> 5;
    const int lane = tid & 31;
    const int g    = lane >> 2;
    const int t    = lane & 3;
    const int arow0 = g * PS_A;
    const int arow8 = arow0 + 8 * PS_A;
    const int brow0 = (16 + g) * PS_A;
    const int brow8 = brow0 + 8 * PS_A;

    float acc0[8][4], acc1[8][4];
    #pragma unroll
    for (int j = 0; j < 8; j++)
        #pragma unroll
        for (int q = 0; q < 4; q++) { acc0[j][q] = 0.f; acc1[j][q] = 0.f; }

    const uint4* bfrag = d_wFrag + (size_t)(cs * 4) * 32 + lane;

    #pragma unroll 6
    for (int s = 0; s < 48; s++) {
        const int k0 = s * 8;
        uint32_t a0 = __float_as_uint(As[arow0 + k0 + t]);
        uint32_t a1 = __float_as_uint(As[arow8 + k0 + t]);
        uint32_t a2 = __float_as_uint(As[arow0 + k0 + t + 4]);
        uint32_t a3 = __float_as_uint(As[arow8 + k0 + t + 4]);
        uint32_t b0 = __float_as_uint(As[brow0 + k0 + t]);
        uint32_t b1 = __float_as_uint(As[brow8 + k0 + t]);
        uint32_t b2 = __float_as_uint(As[brow0 + k0 + t + 4]);
        uint32_t b3 = __float_as_uint(As[brow8 + k0 + t + 4]);
        const uint4* bs = bfrag + (size_t)s * 16 * 32;
        #pragma unroll
        for (int j2 = 0; j2 < 4; j2++) {
            uint4 bv = __ldg(bs + j2 * 32);
            asm volatile(
                "mma.sync.aligned.m16n8k8.row.col.f32.tf32.tf32.f32 "
                "{%0,%1,%2,%3}, {%4,%5,%6,%7}, {%8,%9}, {%0,%1,%2,%3};"
                : "+f"(acc0[2*j2][0]), "+f"(acc0[2*j2][1]),
                  "+f"(acc0[2*j2][2]), "+f"(acc0[2*j2][3])
                : "r"(a0), "r"(a1), "r"(a2), "r"(a3), "r"(bv.x), "r"(bv.y));
            asm volatile(
                "mma.sync.aligned.m16n8k8.row.col.f32.tf32.tf32.f32 "
                "{%0,%1,%2,%3}, {%4,%5,%6,%7}, {%8,%9}, {%0,%1,%2,%3};"
                : "+f"(acc0[2*j2+1][0]), "+f"(acc0[2*j2+1][1]),
                  "+f"(acc0[2*j2+1][2]), "+f"(acc0[2*j2+1][3])
                : "r"(a0), "r"(a1), "r"(a2), "r"(a3), "r"(bv.z), "r"(bv.w));
            asm volatile(
                "mma.sync.aligned.m16n8k8.row.col.f32.tf32.tf32.f32 "
                "{%0,%1,%2,%3}, {%4,%5,%6,%7}, {%8,%9}, {%0,%1,%2,%3};"
                : "+f"(acc1[2*j2][0]), "+f"(acc1[2*j2][1]),
                  "+f"(acc1[2*j2][2]), "+f"(acc1[2*j2][3])
                : "r"(b0), "r"(b1), "r"(b2), "r"(b3), "r"(bv.x), "r"(bv.y));
            asm volatile(
                "mma.sync.aligned.m16n8k8.row.col.f32.tf32.tf32.f32 "
                "{%0,%1,%2,%3}, {%4,%5,%6,%7}, {%8,%9}, {%0,%1,%2,%3};"
                : "+f"(acc1[2*j2+1][0]), "+f"(acc1[2*j2+1][1]),
                  "+f"(acc1[2*j2+1][2]), "+f"(acc1[2*j2+1][3])
                : "r"(b0), "r"(b1), "r"(b2), "r"(b3), "r"(bv.z), "r"(bv.w));
        }
    }

    #pragma unroll
    for (int rt = 0; rt < 2; rt++) {
        float (*acc)[4] = rt ? acc1 : acc0;
        const int mrow0 = m0b + rt * 16 + g;
        #pragma unroll
        for (int j = 0; j < 8; j++) {
            const int n0 = cs * 64 + j * 8 + 2 * t;
            float2 bias = *(const float2*)&d_biasC[n0];
            float o0 = acc[j][0] + bias.x;
            float o1 = acc[j][1] + bias.y;
            float o2 = acc[j][2] + bias.x;
            float o3 = acc[j][3] + bias.y;
            o0 = (o0 >= 0.f) ? o0 : NEGc * o0;
            o1 = (o1 >= 0.f) ? o1 : NEGc * o1;
            o2 = (o2 >= 0.f) ? o2 : NEGc * o2;
            o3 = (o3 >= 0.f) ? o3 : NEGc * o3;
            *(float2*)&out_feat[(size_t)mrow0 * COUTc + n0]       = make_float2(o0, o1);
            *(float2*)&out_feat[(size_t)(mrow0 + 8) * COUTc + n0] = make_float2(o2, o3);
        }
    }
}

// ---------------------------------------------------------------------------
extern "C" void kernel_launch(void* const* d_in, const int* in_sizes, int n_in,
                              void* d_out, int out_size)
{
    const float* xyz     = (const float*)d_in[0];
    const float* feature = (const float*)d_in[1];
    const float* orf     = (const float*)d_in[2];
    const int*   nidx    = (const int*)  d_in[3];
    const float* rel_W   = (const float*)d_in[4];
    const float* rel_b   = (const float*)d_in[5];
    const float* rel_g   = (const float*)d_in[6];
    const float* rel_be  = (const float*)d_in[7];
    const float* rel_m   = (const float*)d_in[8];
    const float* rel_v   = (const float*)d_in[9];
    const float* attn_W  = (const float*)d_in[10];
    const float* out_W   = (const float*)d_in[11];
    const float* out_b   = (const float*)d_in[12];
    const float* out_g   = (const float*)d_in[13];
    const float* out_be  = (const float*)d_in[14];
    const float* out_m   = (const float*)d_in[15];
    const float* out_v   = (const float*)d_in[16];
    const float* sc_W    = (const float*)d_in[17];
    const float* sc_b    = (const float*)d_in[18];
    const float* sc_g    = (const float*)d_in[19];
    const float* sc_be   = (const float*)d_in[20];
    const float* sc_m    = (const float*)d_in[21];
    const float* sc_v    = (const float*)d_in[22];

    float* out = (float*)d_out;

    cudaFuncSetAttribute(lfa_attn_kernel,
                         cudaFuncAttributeMaxDynamicSharedMemorySize, SMA_BYTES);
    cudaFuncSetAttribute(lfa_gemm_kernel,
                         cudaFuncAttributeMaxDynamicSharedMemorySize, GSM_BYTES);

    fuse_and_copy_kernel<<<1024, 256>>>(rel_W, rel_b, rel_g, rel_be, rel_m, rel_v,
                                        out_W, out_b, out_g, out_be, out_m, out_v,
                                        sc_W,  sc_b,  sc_g,  sc_be,  sc_m,  sc_v,
                                        attn_W, xyz, orf, nidx, out);

    lfa_attn_kernel<<<NBLK, NTHR, SMA_BYTES>>>(feature, orf, nidx);

    lfa_gemm_kernel<<<NPTS / GM_TILE, NTHR, GSM_BYTES>>>(feature, out + OFF_OUT);
}

// round 17
// speedup vs baseline: 1.4659x; 1.0100x over previous
#include <cuda_runtime.h>
#include <cuda_bf16.h>
#include <math.h>
#include <stdint.h>

// Problem constants
#define Bq    2
#define Nq    8192
#define Kn    16
#define CINc  128
#define CRc   128
#define Dd    256
#define COUTc 256
#define EPSc  1e-5f
#define NEGc  0.2f
#define LOG2E 1.44269504088896f

#define NPTS  (Bq * Nq)        // 16384 points
#define PPB   8                // points per block (attn kernel)
#define NBLK  (NPTS / PPB)     // 2048 blocks
#define NTHR  128              // attn threads

// Output layout (float32, concatenated)
#define OFF_XYZ   0
#define SZ_XYZ    (Bq * Nq * 3)
#define OFF_OUT   (OFF_XYZ + SZ_XYZ)
#define SZ_OUT    (Bq * Nq * COUTc)
#define OFF_ORF   (OFF_OUT + SZ_OUT)
#define SZ_ORF    (Bq * Nq * Kn * 10)
#define OFF_IDX   (OFF_ORF + SZ_ORF)
#define SZ_IDX    (Bq * Nq * Kn)

// ---- attn kernel shared layout (32-bit words) ----
// PS_FB=132 (pad 4 words): conflict-free ldmatrix. Do not reduce.
#define PS_FB    132
#define SMA_FEAT 0
#define SMA_RELW (SMA_FEAT + 128 * PS_FB)   // 16896
#define SMA_RELB (SMA_RELW + 10 * CRc)      // 18176
#define SMA_IDX  (SMA_RELB + CRc)           // 18304
#define SMA_TOT  (SMA_IDX + 128)            // 18432 words
#define SMA_BYTES (SMA_TOT * 4)             // 73728 B -> 3 blocks/SM

// ---- gemm kernel: 64 points/block, 256 threads (8 warps) ----
#define GM_TILE  64
#define GTHR     256
#define PS_A     388            // As row stride (floats)
#define GSM_BYTES (GM_TILE * PS_A * 4)   // 99328 B -> 2 blocks/SM

// Device globals (no allocation allowed)
__device__ float d_relWf[10 * CRc];
__device__ float d_relB[CRc];
__device__ float d_biasC[COUTc];
// attn_W * log2(e) in bf16 m16n8k16 B-fragment layout:
// e = ((nch*16 + s)*4 + j2)*32 + lane ; uint4 = {b0(j),b1(j),b0(j+1),b1(j+1)}
__device__ uint4 d_attnFrag[4 * 16 * 4 * 32];        // 128 KB
// [outWf ; scWf] (BN-folded) in tf32 m16n8k8 B-fragment layout
__device__ uint4 d_wFrag[48 * 16 * 32];              // 384 KB
// pooled scratch [NPTS][256]
__device__ float d_pooled[(size_t)NPTS * Dd];        // 16.8 MB

__device__ __forceinline__ uint32_t to_tf32(float x) {
    uint32_t r;
    asm("cvt.rna.tf32.f32 %0, %1;" : "=r"(r) : "f"(x));
    return r;
}
__device__ __forceinline__ float to_tf32f(float x) {
    return __uint_as_float(to_tf32(x));
}
__device__ __forceinline__ uint32_t pack_bf2(float lo, float hi) {
    __nv_bfloat162 h = __floats2bfloat162_rn(lo, hi);
    return *reinterpret_cast<uint32_t*>(&h);
}
__device__ __forceinline__ void ldmatrix_x4(uint32_t* d, uint32_t addr) {
    asm volatile("ldmatrix.sync.aligned.m8n8.x4.shared.b16 {%0,%1,%2,%3}, [%4];"
                 : "=r"(d[0]), "=r"(d[1]), "=r"(d[2]), "=r"(d[3]) : "r"(addr));
}
__device__ __forceinline__ uint32_t smem_u32(const void* p) {
    return (uint32_t)__cvta_generic_to_shared(p);
}
__device__ __forceinline__ float2 bf2f(uint32_t u) {
    return __bfloat1622float2(*reinterpret_cast<__nv_bfloat162*>(&u));
}

// folded weight for the combined [outW;scW] GEMM
__device__ __forceinline__ float wc_fold(int k, int n,
    const float* out_W, const float* out_g, const float* out_v,
    const float* sc_W,  const float* sc_g,  const float* sc_v)
{
    if (k < Dd)  return out_W[k * COUTc + n] * out_g[n] * rsqrtf(out_v[n] + EPSc);
    return sc_W[(k - Dd) * COUTc + n] * sc_g[n] * rsqrtf(sc_v[n] + EPSc);
}

// ---------------------------------------------------------------------------
// Setup: fold BN, build fragment tables, passthrough copies (merged)
// ---------------------------------------------------------------------------
__global__ void fuse_and_copy_kernel(
    const float* __restrict__ rel_W, const float* __restrict__ rel_b,
    const float* __restrict__ rel_g, const float* __restrict__ rel_be,
    const float* __restrict__ rel_m, const float* __restrict__ rel_v,
    const float* __restrict__ out_W, const float* __restrict__ out_b,
    const float* __restrict__ out_g, const float* __restrict__ out_be,
    const float* __restrict__ out_m, const float* __restrict__ out_v,
    const float* __restrict__ sc_W,  const float* __restrict__ sc_b,
    const float* __restrict__ sc_g,  const float* __restrict__ sc_be,
    const float* __restrict__ sc_m,  const float* __restrict__ sc_v,
    const float* __restrict__ attn_W,
    const float* __restrict__ xyz,   const float* __restrict__ orf,
    const int*   __restrict__ nidx,  float* __restrict__ out)
{
    int t0 = blockIdx.x * blockDim.x + threadIdx.x;
    int stride = gridDim.x * blockDim.x;

    for (int i = t0; i < 10 * CRc; i += stride) {
        int c = i & (CRc - 1);
        d_relWf[i] = rel_W[i] * rel_g[c] * rsqrtf(rel_v[c] + EPSc);
    }
    for (int i = t0; i < CRc; i += stride) {
        float A = rel_g[i] * rsqrtf(rel_v[i] + EPSc);
        d_relB[i] = (rel_b[i] - rel_m[i]) * A + rel_be[i];
    }
    for (int i = t0; i < COUTc; i += stride) {
        float Ao = out_g[i] * rsqrtf(out_v[i] + EPSc);
        float As = sc_g[i] * rsqrtf(sc_v[i] + EPSc);
        d_biasC[i] = (out_b[i] - out_m[i]) * Ao + out_be[i]
                   + (sc_b[i] - sc_m[i]) * As + sc_be[i];
    }

    // attn bf16 fragment table, pre-scaled by log2(e) (softmax exp -> exp2)
    for (int e = t0; e < 4 * 16 * 4 * 32; e += stride) {
        int lane = e & 31, j2 = (e >> 5) & 3, s = (e >> 7) & 15, nch = e >> 11;
        int g = lane >> 2, tt = lane & 3, k0 = s * 16;
        int n0 = nch * 64 + (2 * j2) * 8 + g;
        int n1 = n0 + 8;
        uint4 v;
        v.x = pack_bf2(LOG2E * attn_W[(k0 + 2*tt)     * Dd + n0],
                       LOG2E * attn_W[(k0 + 2*tt + 1) * Dd + n0]);
        v.y = pack_bf2(LOG2E * attn_W[(k0 + 2*tt + 8) * Dd + n0],
                       LOG2E * attn_W[(k0 + 2*tt + 9) * Dd + n0]);
        v.z = pack_bf2(LOG2E * attn_W[(k0 + 2*tt)     * Dd + n1],
                       LOG2E * attn_W[(k0 + 2*tt + 1) * Dd + n1]);
        v.w = pack_bf2(LOG2E * attn_W[(k0 + 2*tt + 8) * Dd + n1],
                       LOG2E * attn_W[(k0 + 2*tt + 9) * Dd + n1]);
        d_attnFrag[e] = v;
    }

    // combined [outW;scW] tf32 fragment table
    for (int e = t0; e < 48 * 16 * 32; e += stride) {
        int lane = e & 31, j2 = (e >> 5) & 15, s = e >> 9;
        int g = lane >> 2, tt = lane & 3, k0 = s * 8;
        int n0 = (2 * j2) * 8 + g;
        int n1 = n0 + 8;
        uint4 v;
        v.x = to_tf32(wc_fold(k0 + tt,     n0, out_W, out_g, out_v, sc_W, sc_g, sc_v));
        v.y = to_tf32(wc_fold(k0 + tt + 4, n0, out_W, out_g, out_v, sc_W, sc_g, sc_v));
        v.z = to_tf32(wc_fold(k0 + tt,     n1, out_W, out_g, out_v, sc_W, sc_g, sc_v));
        v.w = to_tf32(wc_fold(k0 + tt + 4, n1, out_W, out_g, out_v, sc_W, sc_g, sc_v));
        d_wFrag[e] = v;
    }

    // Passthrough copies
    const float4* xs = (const float4*)xyz;
    float4* xd = (float4*)(out + OFF_XYZ);
    for (int i = t0; i < SZ_XYZ / 4; i += stride) xd[i] = xs[i];
    const float4* os = (const float4*)orf;
    float4* od = (float4*)(out + OFF_ORF);
    for (int i = t0; i < SZ_ORF / 4; i += stride) od[i] = os[i];
    float* id = out + OFF_IDX;
    for (int i = t0; i < SZ_IDX; i += stride) id[i] = (float)nidx[i];
}

// ---------------------------------------------------------------------------
// Attention kernel (r15-proven, best known): 8 points/block, 128 threads.
// ---------------------------------------------------------------------------
__global__ __launch_bounds__(NTHR, 3)
void lfa_attn_kernel(const float* __restrict__ feature,
                     const float* __restrict__ orf,
                     const int*   __restrict__ nidx)
{
    extern __shared__ uint32_t smem[];
    uint32_t* feat_b = smem + SMA_FEAT;           // [128][PS_FB] bf16x2
    float* relW_s = (float*)(smem + SMA_RELW);    // [10][128]
    float* relB_s = (float*)(smem + SMA_RELB);    // [128]
    int*   idx_s  = (int*)(smem + SMA_IDX);       // [128]

    const int tid = threadIdx.x;
    const int p0  = blockIdx.x * PPB;
    const int b   = p0 >> 13;

    idx_s[tid] = nidx[p0 * Kn + tid];
    for (int i = tid; i < 10 * CRc; i += NTHR) relW_s[i] = d_relWf[i];
    if (tid < CRc) relB_s[tid] = d_relB[tid];
    __syncthreads();

    const float* fbase = feature + (size_t)b * Nq * CINc;
    for (int i = tid; i < 128 * 32; i += NTHR) {
        int r = i >> 5, c4 = i & 31;
        float4 v = *((const float4*)(fbase + (size_t)idx_s[r] * CINc) + c4);
        uint2 pk;
        pk.x = pack_bf2(v.x, v.y);
        pk.y = pack_bf2(v.z, v.w);
        *(uint2*)&feat_b[r * PS_FB + c4 * 2] = pk;
    }

    {
        const int r = tid;
        float o[10];
        const float* orow = orf + (size_t)p0 * 160 + r * 10;
        #pragma unroll
        for (int d = 0; d < 10; d++) o[d] = orow[d];
        uint32_t* frow = &feat_b[r * PS_FB + 64];
        #pragma unroll 4
        for (int c2 = 0; c2 < 64; c2++) {
            float a0 = relB_s[2 * c2], a1 = relB_s[2 * c2 + 1];
            #pragma unroll
            for (int d = 0; d < 10; d++) {
                float2 wv = *(const float2*)&relW_s[d * CRc + 2 * c2];
                a0 += o[d] * wv.x;
                a1 += o[d] * wv.y;
            }
            a0 = (a0 >= 0.f) ? a0 : NEGc * a0;
            a1 = (a1 >= 0.f) ? a1 : NEGc * a1;
            frow[c2] = pack_bf2(a0, a1);
        }
    }
    __syncthreads();

    const int w    = tid >> 5;
    const int lane = tid & 31;
    const int g    = lane >> 2;
    const int t    = lane & 3;

    const int row16 = (lane & 7) | (((lane >> 3) & 1) << 3);
    const int khalf = lane >> 4;
    const uint32_t fb_base = smem_u32(feat_b);
    const uint32_t abase0 = fb_base + (((2*w)   * 16 + row16) * PS_FB + khalf * 4) * 4;
    const uint32_t abase1 = fb_base + (((2*w+1) * 16 + row16) * PS_FB + khalf * 4) * 4;

    const int prow0_0 = ((2*w)   * 16 + g) * PS_FB, prow8_0 = prow0_0 + 8 * PS_FB;
    const int prow0_1 = ((2*w+1) * 16 + g) * PS_FB, prow8_1 = prow0_1 + 8 * PS_FB;
    float* poolrow0 = d_pooled + (size_t)(p0 + 2*w)     * Dd;
    float* poolrow1 = d_pooled + (size_t)(p0 + 2*w + 1) * Dd;

    #pragma unroll 1
    for (int nch = 0; nch < 4; nch++) {
        float acc0[8][4], acc1[8][4];
        #pragma unroll
        for (int j = 0; j < 8; j++)
            #pragma unroll
            for (int q = 0; q < 4; q++) { acc0[j][q] = 0.f; acc1[j][q] = 0.f; }

        const uint4* bfrag = d_attnFrag + (size_t)(nch * 16) * 128 + lane;

        uint4 bcur[4], bnxt[4];
        #pragma unroll
        for (int j2 = 0; j2 < 4; j2++) bcur[j2] = __ldg(bfrag + j2 * 32);

        #pragma unroll
        for (int s = 0; s < 16; s++) {
            if (s < 15) {
                const uint4* bs = bfrag + (s + 1) * 128;
                #pragma unroll
                for (int j2 = 0; j2 < 4; j2++) bnxt[j2] = __ldg(bs + j2 * 32);
            }

            uint32_t A0[4], A1[4];
            ldmatrix_x4(A0, abase0 + s * 32);
            ldmatrix_x4(A1, abase1 + s * 32);

            #pragma unroll
            for (int j2 = 0; j2 < 4; j2++) {
                uint4 bv = bcur[j2];
                asm volatile(
                    "mma.sync.aligned.m16n8k16.row.col.f32.bf16.bf16.f32 "
                    "{%0,%1,%2,%3}, {%4,%5,%6,%7}, {%8,%9}, {%0,%1,%2,%3};"
                    : "+f"(acc0[2*j2][0]), "+f"(acc0[2*j2][1]),
                      "+f"(acc0[2*j2][2]), "+f"(acc0[2*j2][3])
                    : "r"(A0[0]), "r"(A0[1]), "r"(A0[2]), "r"(A0[3]), "r"(bv.x), "r"(bv.y));
                asm volatile(
                    "mma.sync.aligned.m16n8k16.row.col.f32.bf16.bf16.f32 "
                    "{%0,%1,%2,%3}, {%4,%5,%6,%7}, {%8,%9}, {%0,%1,%2,%3};"
                    : "+f"(acc1[2*j2][0]), "+f"(acc1[2*j2][1]),
                      "+f"(acc1[2*j2][2]), "+f"(acc1[2*j2][3])
                    : "r"(A1[0]), "r"(A1[1]), "r"(A1[2]), "r"(A1[3]), "r"(bv.x), "r"(bv.y));
                asm volatile(
                    "mma.sync.aligned.m16n8k16.row.col.f32.bf16.bf16.f32 "
                    "{%0,%1,%2,%3}, {%4,%5,%6,%7}, {%8,%9}, {%0,%1,%2,%3};"
                    : "+f"(acc0[2*j2+1][0]), "+f"(acc0[2*j2+1][1]),
                      "+f"(acc0[2*j2+1][2]), "+f"(acc0[2*j2+1][3])
                    : "r"(A0[0]), "r"(A0[1]), "r"(A0[2]), "r"(A0[3]), "r"(bv.z), "r"(bv.w));
                asm volatile(
                    "mma.sync.aligned.m16n8k16.row.col.f32.bf16.bf16.f32 "
                    "{%0,%1,%2,%3}, {%4,%5,%6,%7}, {%8,%9}, {%0,%1,%2,%3};"
                    : "+f"(acc1[2*j2+1][0]), "+f"(acc1[2*j2+1][1]),
                      "+f"(acc1[2*j2+1][2]), "+f"(acc1[2*j2+1][3])
                    : "r"(A1[0]), "r"(A1[1]), "r"(A1[2]), "r"(A1[3]), "r"(bv.z), "r"(bv.w));
            }

            #pragma unroll
            for (int j2 = 0; j2 < 4; j2++) bcur[j2] = bnxt[j2];
        }

        #pragma unroll
        for (int pt = 0; pt < 2; pt++) {
            float (*acc)[4] = pt ? acc1 : acc0;
            const int prow0 = pt ? prow0_1 : prow0_0;
            const int prow8 = pt ? prow8_1 : prow8_0;
            float* poolrow = pt ? poolrow1 : poolrow0;
            #pragma unroll
            for (int j = 0; j < 8; j++) {
                float e0 = exp2f(acc[j][0]);
                float e1 = exp2f(acc[j][1]);
                float e2 = exp2f(acc[j][2]);
                float e3 = exp2f(acc[j][3]);

                uint32_t u01 = feat_b[prow0 + nch * 32 + j * 4 + t];
                uint32_t u23 = feat_b[prow8 + nch * 32 + j * 4 + t];
                float2 f01 = bf2f(u01);
                float2 f23 = bf2f(u23);

                float s0  = e0 + e2;
                float s1  = e1 + e3;
                float pp0 = e0 * f01.x + e2 * f23.x;
                float pp1 = e1 * f01.y + e3 * f23.y;

                #pragma unroll
                for (int d = 4; d <= 16; d <<= 1) {
                    s0  += __shfl_xor_sync(0xffffffffu, s0, d);
                    s1  += __shfl_xor_sync(0xffffffffu, s1, d);
                    pp0 += __shfl_xor_sync(0xffffffffu, pp0, d);
                    pp1 += __shfl_xor_sync(0xffffffffu, pp1, d);
                }

                if (g == 0) {
                    const int C = nch * 64 + j * 8 + 2 * t;
                    *(float2*)&poolrow[C] =
                        make_float2(__fdividef(pp0, s0), __fdividef(pp1, s1));
                }
            }
        }
    }
}

// ---------------------------------------------------------------------------
// Final GEMM: 64 points/block, 256 threads (8 warps).
// warp w: rt2 = w>>2 (32-row half), cs = w&3 (64-col segment); 2 m16 tiles.
// Halves the per-launch d_wFrag L2 stream vs GM_TILE=32.
// ---------------------------------------------------------------------------
__global__ __launch_bounds__(GTHR, 2)
void lfa_gemm_kernel(const float* __restrict__ feature,
                     float*       __restrict__ out_feat)
{
    extern __shared__ float As[];      // [64][PS_A]

    const int tid = threadIdx.x;
    const int m0b = blockIdx.x * GM_TILE;

    for (int i = tid; i < GM_TILE * 96; i += GTHR) {
        int row = i / 96, q = i % 96;
        int m = m0b + row;
        float4 v;
        if (q < 64) v = *((const float4*)(d_pooled + (size_t)m * Dd) + q);
        else        v = *((const float4*)(feature + (size_t)m * CINc) + (q - 64));
        v.x = to_tf32f(v.x); v.y = to_tf32f(v.y);
        v.z = to_tf32f(v.z); v.w = to_tf32f(v.w);
        *(float4*)&As[row * PS_A + q * 4] = v;
    }
    __syncthreads();

    const int w    = tid >> 5;
    const int rt2  = w >> 2;            // 0..1: 32-row half
    const int cs   = w & 3;             // 0..3: 64-col segment
    const int lane = tid & 31;
    const int g    = lane >> 2;
    const int t    = lane & 3;
    const int rbase = rt2 * 32;
    const int arow0 = (rbase + g) * PS_A;
    const int arow8 = arow0 + 8 * PS_A;
    const int brow0 = (rbase + 16 + g) * PS_A;
    const int brow8 = brow0 + 8 * PS_A;

    float acc0[8][4], acc1[8][4];
    #pragma unroll
    for (int j = 0; j < 8; j++)
        #pragma unroll
        for (int q = 0; q < 4; q++) { acc0[j][q] = 0.f; acc1[j][q] = 0.f; }

    const uint4* bfrag = d_wFrag + (size_t)(cs * 4) * 32 + lane;

    #pragma unroll 6
    for (int s = 0; s < 48; s++) {
        const int k0 = s * 8;
        uint32_t a0 = __float_as_uint(As[arow0 + k0 + t]);
        uint32_t a1 = __float_as_uint(As[arow8 + k0 + t]);
        uint32_t a2 = __float_as_uint(As[arow0 + k0 + t + 4]);
        uint32_t a3 = __float_as_uint(As[arow8 + k0 + t + 4]);
        uint32_t b0 = __float_as_uint(As[brow0 + k0 + t]);
        uint32_t b1 = __float_as_uint(As[brow8 + k0 + t]);
        uint32_t b2 = __float_as_uint(As[brow0 + k0 + t + 4]);
        uint32_t b3 = __float_as_uint(As[brow8 + k0 + t + 4]);
        const uint4* bs = bfrag + (size_t)s * 16 * 32;
        #pragma unroll
        for (int j2 = 0; j2 < 4; j2++) {
            uint4 bv = __ldg(bs + j2 * 32);
            asm volatile(
                "mma.sync.aligned.m16n8k8.row.col.f32.tf32.tf32.f32 "
                "{%0,%1,%2,%3}, {%4,%5,%6,%7}, {%8,%9}, {%0,%1,%2,%3};"
                : "+f"(acc0[2*j2][0]), "+f"(acc0[2*j2][1]),
                  "+f"(acc0[2*j2][2]), "+f"(acc0[2*j2][3])
                : "r"(a0), "r"(a1), "r"(a2), "r"(a3), "r"(bv.x), "r"(bv.y));
            asm volatile(
                "mma.sync.aligned.m16n8k8.row.col.f32.tf32.tf32.f32 "
                "{%0,%1,%2,%3}, {%4,%5,%6,%7}, {%8,%9}, {%0,%1,%2,%3};"
                : "+f"(acc0[2*j2+1][0]), "+f"(acc0[2*j2+1][1]),
                  "+f"(acc0[2*j2+1][2]), "+f"(acc0[2*j2+1][3])
                : "r"(a0), "r"(a1), "r"(a2), "r"(a3), "r"(bv.z), "r"(bv.w));
            asm volatile(
                "mma.sync.aligned.m16n8k8.row.col.f32.tf32.tf32.f32 "
                "{%0,%1,%2,%3}, {%4,%5,%6,%7}, {%8,%9}, {%0,%1,%2,%3};"
                : "+f"(acc1[2*j2][0]), "+f"(acc1[2*j2][1]),
                  "+f"(acc1[2*j2][2]), "+f"(acc1[2*j2][3])
                : "r"(b0), "r"(b1), "r"(b2), "r"(b3), "r"(bv.x), "r"(bv.y));
            asm volatile(
                "mma.sync.aligned.m16n8k8.row.col.f32.tf32.tf32.f32 "
                "{%0,%1,%2,%3}, {%4,%5,%6,%7}, {%8,%9}, {%0,%1,%2,%3};"
                : "+f"(acc1[2*j2+1][0]), "+f"(acc1[2*j2+1][1]),
                  "+f"(acc1[2*j2+1][2]), "+f"(acc1[2*j2+1][3])
                : "r"(b0), "r"(b1), "r"(b2), "r"(b3), "r"(bv.z), "r"(bv.w));
        }
    }

    #pragma unroll
    for (int rt = 0; rt < 2; rt++) {
        float (*acc)[4] = rt ? acc1 : acc0;
        const int mrow0 = m0b + rt2 * 32 + rt * 16 + g;
        #pragma unroll
        for (int j = 0; j < 8; j++) {
            const int n0 = cs * 64 + j * 8 + 2 * t;
            float2 bias = *(const float2*)&d_biasC[n0];
            float o0 = acc[j][0] + bias.x;
            float o1 = acc[j][1] + bias.y;
            float o2 = acc[j][2] + bias.x;
            float o3 = acc[j][3] + bias.y;
            o0 = (o0 >= 0.f) ? o0 : NEGc * o0;
            o1 = (o1 >= 0.f) ? o1 : NEGc * o1;
            o2 = (o2 >= 0.f) ? o2 : NEGc * o2;
            o3 = (o3 >= 0.f) ? o3 : NEGc * o3;
            *(float2*)&out_feat[(size_t)mrow0 * COUTc + n0]       = make_float2(o0, o1);
            *(float2*)&out_feat[(size_t)(mrow0 + 8) * COUTc + n0] = make_float2(o2, o3);
        }
    }
}

// ---------------------------------------------------------------------------
extern "C" void kernel_launch(void* const* d_in, const int* in_sizes, int n_in,
                              void* d_out, int out_size)
{
    const float* xyz     = (const float*)d_in[0];
    const float* feature = (const float*)d_in[1];
    const float* orf     = (const float*)d_in[2];
    const int*   nidx    = (const int*)  d_in[3];
    const float* rel_W   = (const float*)d_in[4];
    const float* rel_b   = (const float*)d_in[5];
    const float* rel_g   = (const float*)d_in[6];
    const float* rel_be  = (const float*)d_in[7];
    const float* rel_m   = (const float*)d_in[8];
    const float* rel_v   = (const float*)d_in[9];
    const float* attn_W  = (const float*)d_in[10];
    const float* out_W   = (const float*)d_in[11];
    const float* out_b   = (const float*)d_in[12];
    const float* out_g   = (const float*)d_in[13];
    const float* out_be  = (const float*)d_in[14];
    const float* out_m   = (const float*)d_in[15];
    const float* out_v   = (const float*)d_in[16];
    const float* sc_W    = (const float*)d_in[17];
    const float* sc_b    = (const float*)d_in[18];
    const float* sc_g    = (const float*)d_in[19];
    const float* sc_be   = (const float*)d_in[20];
    const float* sc_m    = (const float*)d_in[21];
    const float* sc_v    = (const float*)d_in[22];

    float* out = (float*)d_out;

    cudaFuncSetAttribute(lfa_attn_kernel,
                         cudaFuncAttributeMaxDynamicSharedMemorySize, SMA_BYTES);
    cudaFuncSetAttribute(lfa_gemm_kernel,
                         cudaFuncAttributeMaxDynamicSharedMemorySize, GSM_BYTES);

    fuse_and_copy_kernel<<<1024, 256>>>(rel_W, rel_b, rel_g, rel_be, rel_m, rel_v,
                                        out_W, out_b, out_g, out_be, out_m, out_v,
                                        sc_W,  sc_b,  sc_g,  sc_be,  sc_m,  sc_v,
                                        attn_W, xyz, orf, nidx, out);

    lfa_attn_kernel<<<NBLK, NTHR, SMA_BYTES>>>(feature, orf, nidx);

    lfa_gemm_kernel<<<NPTS / GM_TILE, GTHR, GSM_BYTES>>>(feature, out + OFF_OUT);
}